// round 11
// baseline (speedup 1.0000x reference)
#include <cuda_runtime.h>
#include <cuda_bf16.h>
#include <cstdint>

#define HID   1024
#define BATCH 64
#define SEQ   512
#define G3    3072
#define BT    (BATCH * SEQ)
#define DIN0  118

#define NBLK  128          // persistent blocks (all co-resident; <= 148 SMs)
#define GNT   256          // 8 warps: mt = warp&3 (m-tile), wgk = warp>>2 (k-half)
#define GKC   64           // k rows per staged h chunk (each wgk computes 32)
#define GHROW 68           // floats per smem h k-row (64 + 4 pad)
#define NSTG  4            // h ring stages
#define NGRP  (HID / GKC)  // 16 chunk groups; group g produced by blocks 8g..8g+7
// smem: W_hi u32[1024][24] (96KB) + h ring 4*64*68*4 (69632) + W_lo u16[1024][24] (48KB)
#define WHI_WORDS (HID * 24)
#define HBUF_FLOATS (GKC * GHROW)
#define SM_WHI_OFF 0
#define SM_HB_OFF  (WHI_WORDS * 4)                         // 98304
#define SM_WLO_OFF (SM_HB_OFF + NSTG * HBUF_FLOATS * 4)    // 167936
#define GSM_BYTES  (SM_WLO_OFF + HID * 24 * 2)             // 217088

// ---------------- scratch (device globals; no allocation allowed) ----------
__device__ float  g_xg[(size_t)BT * G3];      // input projections for current layer
__device__ float  g_yA[(size_t)BT * HID];     // layer outputs ping
__device__ float  g_yB[(size_t)BT * HID];     // layer outputs pong
__device__ float  g_hT[2][HID * BATCH];       // hidden fp32, [k][b], ping-pong
__device__ float  g_hb[BATCH * HID];          // final hidden, batch-major
__device__ unsigned long long g_rdy[NGRP * 16];    // per-group arrival counters (128B stride)
__device__ unsigned long long g_selfep[NBLK * 16]; // per-block completed-step count

__device__ __forceinline__ float fsigmoid(float x) {
    return 1.f / (1.f + __expf(-x));
}
__device__ __forceinline__ float ftanh(float x) {
    return 2.f / (1.f + __expf(-2.f * x)) - 1.f;
}

// ---------------------------------------------------------------------------
// cp.async / tf32 helpers
// ---------------------------------------------------------------------------
__device__ __forceinline__ void cp_async16(uint32_t smem_dst, const void* gptr) {
    asm volatile("cp.async.cg.shared.global [%0], [%1], 16;\n"
                 :: "r"(smem_dst), "l"(gptr));
}
__device__ __forceinline__ void cp_commit() {
    asm volatile("cp.async.commit_group;\n");
}
template <int N>
__device__ __forceinline__ void cp_wait() {
    asm volatile("cp.async.wait_group %0;\n" :: "n"(N));
}
__device__ __forceinline__ uint32_t f2tf32(float x) {
    uint32_t r;
    asm("cvt.rna.tf32.f32 %0, %1;" : "=r"(r) : "f"(x));
    return r;
}
__device__ __forceinline__ void mma_tf32(
    float& c0, float& c1, float& c2, float& c3,
    uint32_t a0, uint32_t a1, uint32_t a2, uint32_t a3,
    uint32_t b0, uint32_t b1)
{
    asm volatile(
        "mma.sync.aligned.m16n8k8.row.col.f32.tf32.tf32.f32 "
        "{%0,%1,%2,%3}, {%4,%5,%6,%7}, {%8,%9}, {%0,%1,%2,%3};"
        : "+f"(c0), "+f"(c1), "+f"(c2), "+f"(c3)
        : "r"(a0), "r"(a1), "r"(a2), "r"(a3), "r"(b0), "r"(b1));
}

// wait until chunk group grp has all 8 producer arrivals for this step.
// lane 0 of each warp polls; warp converges at syncwarp.
__device__ __forceinline__ void wait_rdy(int grp, unsigned long long target) {
    if ((threadIdx.x & 31) == 0) {
        while (*(volatile unsigned long long*)&g_rdy[grp * 16] < target)
            __nanosleep(32);
        __threadfence();   // acquire: order subsequent h reads after the flag
    }
    __syncwarp();
}

// ---------------------------------------------------------------------------
// Persistent per-layer GRU kernel — tf32x3 mma recurrence, NO global barrier:
// fine-grained producer->consumer dataflow on h chunk groups.
//   producer: block bid writes h cols 8bid..8bid+7 (group bid/8), then
//             fence + atomicAdd(g_rdy[group]).
//   consumer: before staging chunk c of step t, wait g_rdy[c] >= 8*(ep0+t).
// Safety: a block reaches its h[t+1] write only after consuming ALL of h[t],
// which implies every block finished step t-1's reads of the slot being
// overwritten (ping-pong depth 2 suffices).
// ---------------------------------------------------------------------------
__global__ __launch_bounds__(GNT, 1) void gru_layer_kernel(
    const float* __restrict__ Whh, const float* __restrict__ bhh, int ysel)
{
    extern __shared__ char smraw[];
    uint32_t* W_hi = (uint32_t*)(smraw + SM_WHI_OFF);   // [k*24 + j]
    float*    HBf  = (float*)(smraw + SM_HB_OFF);       // 4 x [64][68]
    uint16_t* W_lo = (uint16_t*)(smraw + SM_WLO_OFF);   // [k*24 + j] bf16 bits

    const int tid  = threadIdx.x;
    const int bid  = blockIdx.x;
    const int c0   = bid * 8;
    const int warp = tid >> 5;
    const int lane = tid & 31;
    const int mt   = warp & 3;                 // m-tile
    const int wgk  = warp >> 2;                // k-half within chunk (0/1)
    const int l4   = lane >> 2;                // 0..7
    const int tq   = lane & 3;                 // 0..3
    const int mygrp = bid >> 3;                // chunk group this block produces

    // per-launch epoch base: own flag, written only by self at end of launch.
    const unsigned long long ep0 =
        *(volatile unsigned long long*)&g_selfep[bid * 16];

    // ---- pre-split Whh slice: hi = tf32(w) (u32), lo = bf16(w - hi) ----
    for (int idx = tid; idx < 24 * HID; idx += GNT) {
        int j = idx >> 10;                     // 0..23 = gate*8 + col
        int k = idx & (HID - 1);
        int jg = j >> 3, jc = j & 7;
        float w  = Whh[(size_t)(jg * HID + c0 + jc) * HID + k];
        uint32_t wh = f2tf32(w);
        W_hi[k * 24 + j] = wh;
        __nv_bfloat16 wl = __float2bfloat16(w - __uint_as_float(wh));
        W_lo[k * 24 + j] = *(uint16_t*)&wl;
    }

    // gate constants (used by wg0 only)
    const int cA = c0 + 2 * tq;
    const int bA = mt * 16 + l4;
    float bh[3][2];
#pragma unroll
    for (int gte = 0; gte < 3; gte++) {
        bh[gte][0] = bhh[gte * HID + cA];
        bh[gte][1] = bhh[gte * HID + cA + 1];
    }

    float hp[4] = {0.f, 0.f, 0.f, 0.f};        // h_prev cells (wg0)

    const uint32_t s_hb = (uint32_t)__cvta_generic_to_shared(HBf);
    __syncthreads();                           // W smem ready (block-local)

    for (int t = 0; t < SEQ; t++) {
        // ---- prefetch xg for this step's gate cells (wg0 only) ----
        float xv[3][4];
        if (wgk == 0) {
            const size_t rA = ((size_t)bA * SEQ + t) * G3;
            const size_t rB = ((size_t)(bA + 8) * SEQ + t) * G3;
#pragma unroll
            for (int gte = 0; gte < 3; gte++) {
                xv[gte][0] = __ldcg(&g_xg[rA + gte * HID + cA]);
                xv[gte][1] = __ldcg(&g_xg[rA + gte * HID + cA + 1]);
                xv[gte][2] = __ldcg(&g_xg[rB + gte * HID + cA]);
                xv[gte][3] = __ldcg(&g_xg[rB + gte * HID + cA + 1]);
            }
        }

        float acc[3][4];
#pragma unroll
        for (int nt = 0; nt < 3; nt++)
#pragma unroll
            for (int r = 0; r < 4; r++) acc[nt][r] = 0.f;

        if (t > 0) {
            const float* hsrc = g_hT[t & 1];
            const unsigned long long tgt =
                8ull * (ep0 + (unsigned long long)t);

            // prologue: stage chunks 0,1,2 (each gated on its producer group)
#pragma unroll
            for (int ch = 0; ch < NSTG - 1; ch++) {
                wait_rdy(ch, tgt);
                uint32_t dst = s_hb + (uint32_t)ch * (HBUF_FLOATS * 4);
                const float* src = hsrc + (size_t)ch * GKC * BATCH;
#pragma unroll
                for (int j = 0; j < (GKC * 16) / GNT; j++) {   // 4 ops/thread
                    int o = tid + j * GNT;
                    int k = o >> 4, s = o & 15;
                    cp_async16(dst + (uint32_t)(k * GHROW + s * 4) * 4,
                               src + (size_t)k * BATCH + s * 4);
                }
                cp_commit();
            }

#pragma unroll 1
            for (int ch = 0; ch < NGRP; ch++) {                // 16 chunks
                cp_wait<NSTG - 2>();           // chunk ch resident
                __syncthreads();               // single sync per chunk
                const float* hb = HBf + (ch & 3) * HBUF_FLOATS + wgk * 32 * GHROW;
                const int kg = ch * GKC + wgk * 32;

#pragma unroll
                for (int ks = 0; ks < 4; ks++) {
                    const int kk = ks * 8;
                    // A fragments (h fp32 -> hi/lo on the fly)
                    float a0 = hb[(kk + tq) * GHROW + bA];
                    float a1 = hb[(kk + tq) * GHROW + bA + 8];
                    float a2 = hb[(kk + tq + 4) * GHROW + bA];
                    float a3 = hb[(kk + tq + 4) * GHROW + bA + 8];
                    uint32_t ah0 = f2tf32(a0), al0 = f2tf32(a0 - __uint_as_float(ah0));
                    uint32_t ah1 = f2tf32(a1), al1 = f2tf32(a1 - __uint_as_float(ah1));
                    uint32_t ah2 = f2tf32(a2), al2 = f2tf32(a2 - __uint_as_float(ah2));
                    uint32_t ah3 = f2tf32(a3), al3 = f2tf32(a3 - __uint_as_float(ah3));
#pragma unroll
                    for (int nt = 0; nt < 3; nt++) {
                        int j = nt * 8 + l4;
                        int w0 = (kg + kk + tq) * 24 + j;
                        int w1 = (kg + kk + tq + 4) * 24 + j;
                        uint32_t bh0 = W_hi[w0];
                        uint32_t bh1 = W_hi[w1];
                        uint32_t bl0 = ((uint32_t)W_lo[w0]) << 16;
                        uint32_t bl1 = ((uint32_t)W_lo[w1]) << 16;
                        float* c = acc[nt];
                        mma_tf32(c[0], c[1], c[2], c[3], ah0, ah1, ah2, ah3, bh0, bh1);
                        mma_tf32(c[0], c[1], c[2], c[3], ah0, ah1, ah2, ah3, bl0, bl1);
                        mma_tf32(c[0], c[1], c[2], c[3], al0, al1, al2, al3, bh0, bh1);
                    }
                }
                // stage chunk ch+3 into ring slot (ch+3)&3
                if (ch + NSTG - 1 < NGRP) {
                    int cn = ch + NSTG - 1;
                    wait_rdy(cn, tgt);         // mostly instant past prologue
                    uint32_t dst = s_hb + (uint32_t)(cn & 3) * (HBUF_FLOATS * 4);
                    const float* src = hsrc + (size_t)cn * GKC * BATCH;
#pragma unroll
                    for (int j = 0; j < (GKC * 16) / GNT; j++) {
                        int o = tid + j * GNT;
                        int k = o >> 4, s = o & 15;
                        cp_async16(dst + (uint32_t)(k * GHROW + s * 4) * 4,
                                   src + (size_t)k * BATCH + s * 4);
                    }
                }
                cp_commit();                   // uniform (possibly empty) commit
            }

            // ---- cross-warpgroup acc reduction (reuse h ring as scratch) ----
            cp_wait<0>();
            __syncthreads();
            float* red = HBf;                  // 128 threads x 12 floats
            if (wgk == 1) {
                int o = (mt * 32 + lane) * 12;
#pragma unroll
                for (int nt = 0; nt < 3; nt++)
#pragma unroll
                    for (int r = 0; r < 4; r++)
                        red[o + nt * 4 + r] = acc[nt][r];
            }
            __syncthreads();
            if (wgk == 0) {
                int o = (mt * 32 + lane) * 12;
#pragma unroll
                for (int nt = 0; nt < 3; nt++)
#pragma unroll
                    for (int r = 0; r < 4; r++)
                        acc[nt][r] += red[o + nt * 4 + r];
            }
        }

        // ---- gates, in register (wg0 only) ----
        if (wgk == 0) {
            float* hdst = g_hT[(t + 1) & 1];
#pragma unroll
            for (int r = 0; r < 4; r++) {
                int i  = r >> 1, jj = r & 1;
                int b  = bA + 8 * i;
                int cc = cA + jj;
                int ar = 2 * i + jj;
                float rg = fsigmoid(xv[0][2 * i + jj] + acc[0][ar] + bh[0][jj]);
                float zg = fsigmoid(xv[1][2 * i + jj] + acc[1][ar] + bh[1][jj]);
                float ng = ftanh(xv[2][2 * i + jj] + rg * (acc[2][ar] + bh[2][jj]));
                float h  = (1.f - zg) * ng + zg * hp[r];
                hp[r] = h;

                hdst[(size_t)cc * BATCH + b] = h;

                size_t bt = (size_t)b * SEQ + t;
                if (ysel == 1)      g_yA[bt * HID + cc] = h;
                else if (ysel == 2) g_yB[bt * HID + cc] = h;
                if (t == SEQ - 1)   g_hb[(size_t)b * HID + cc] = h;
            }
        }

        // publish this block's h[t+1] group: release-fence then arrive.
        __threadfence();                 // every writer fences its h stores
        __syncthreads();                 // block-wide completion
        if (tid == 0)
            atomicAdd(&g_rdy[mygrp * 16], 1ull);
        // no global barrier: next step's chunk polls provide all ordering.
    }

    if (tid == 0)
        *(volatile unsigned long long*)&g_selfep[bid * 16] = ep0 + SEQ;
}

// ---------------------------------------------------------------------------
// tf32 split-3 MMA GEMM for xg of layers 1,2 (K = 1024). (unchanged, passing)
// ---------------------------------------------------------------------------
#define XKC   32
#define XLD   36
#define XA_F  (128 * XLD)
#define XB_F  (64 * XLD)
#define XST_F (XA_F + XB_F)

__global__ __launch_bounds__(128, 2) void gemm_xg_tf32_kernel(
    int a_sel, const float* __restrict__ W, const float* __restrict__ bias)
{
    const float* A = (a_sel == 1) ? g_yA : g_yB;
    const int K = HID;

    extern __shared__ float xs[];
    const int tid  = threadIdx.x;
    const int warp = tid >> 5;
    const int lane = tid & 31;
    const int g    = lane >> 2;
    const int tq   = lane & 3;

    const int n0 = blockIdx.x * 64;
    const int m0 = blockIdx.y * 128;
    const int wm = (warp & 1) * 64;
    const int wn = (warp >> 1) * 32;

    const uint32_t s_base = (uint32_t)__cvta_generic_to_shared(xs);

    float acc[4][4][4];
#pragma unroll
    for (int mi = 0; mi < 4; mi++)
#pragma unroll
        for (int ni = 0; ni < 4; ni++)
#pragma unroll
            for (int r = 0; r < 4; r++) acc[mi][ni][r] = 0.f;

    auto load_stage = [&](int ch, int buf) {
        const int k0 = ch * XKC;
        uint32_t dstA = s_base + (uint32_t)buf * XST_F * 4;
        uint32_t dstB = dstA + XA_F * 4;
#pragma unroll
        for (int j = 0; j < 8; j++) {
            int o = tid + j * 128;
            int row = o >> 3, seg = o & 7;
            cp_async16(dstA + (uint32_t)(row * XLD + seg * 4) * 4,
                       A + (size_t)(m0 + row) * K + k0 + seg * 4);
        }
#pragma unroll
        for (int j = 0; j < 4; j++) {
            int o = tid + j * 128;
            int row = o >> 3, seg = o & 7;
            cp_async16(dstB + (uint32_t)(row * XLD + seg * 4) * 4,
                       W + (size_t)(n0 + row) * K + k0 + seg * 4);
        }
    };

    const int NCH = K / XKC;
    load_stage(0, 0); cp_commit();
    load_stage(1, 1); cp_commit();

    for (int ch = 0; ch < NCH; ch++) {
        cp_wait<1>();
        __syncthreads();
        const float* As = xs + (ch & 1) * XST_F;
        const float* Bs = As + XA_F;

#pragma unroll
        for (int ks = 0; ks < 4; ks++) {
            const int k = ks * 8;
            uint32_t ahi[4][4], alo[4][4];
#pragma unroll
            for (int mi = 0; mi < 4; mi++) {
                int rbase = wm + mi * 16 + g;
                float r0 = As[(rbase)     * XLD + k + tq];
                float r1 = As[(rbase + 8) * XLD + k + tq];
                float r2 = As[(rbase)     * XLD + k + tq + 4];
                float r3 = As[(rbase + 8) * XLD + k + tq + 4];
                ahi[mi][0] = f2tf32(r0); alo[mi][0] = f2tf32(r0 - __uint_as_float(ahi[mi][0]));
                ahi[mi][1] = f2tf32(r1); alo[mi][1] = f2tf32(r1 - __uint_as_float(ahi[mi][1]));
                ahi[mi][2] = f2tf32(r2); alo[mi][2] = f2tf32(r2 - __uint_as_float(ahi[mi][2]));
                ahi[mi][3] = f2tf32(r3); alo[mi][3] = f2tf32(r3 - __uint_as_float(ahi[mi][3]));
            }
            uint32_t bhi[4][2], blo[4][2];
#pragma unroll
            for (int ni = 0; ni < 4; ni++) {
                int nbase = wn + ni * 8 + g;
                float r0 = Bs[nbase * XLD + k + tq];
                float r1 = Bs[nbase * XLD + k + tq + 4];
                bhi[ni][0] = f2tf32(r0); blo[ni][0] = f2tf32(r0 - __uint_as_float(bhi[ni][0]));
                bhi[ni][1] = f2tf32(r1); blo[ni][1] = f2tf32(r1 - __uint_as_float(bhi[ni][1]));
            }
#pragma unroll
            for (int mi = 0; mi < 4; mi++)
#pragma unroll
                for (int ni = 0; ni < 4; ni++) {
                    float* c = acc[mi][ni];
                    mma_tf32(c[0], c[1], c[2], c[3],
                             ahi[mi][0], ahi[mi][1], ahi[mi][2], ahi[mi][3],
                             bhi[ni][0], bhi[ni][1]);
                    mma_tf32(c[0], c[1], c[2], c[3],
                             ahi[mi][0], ahi[mi][1], ahi[mi][2], ahi[mi][3],
                             blo[ni][0], blo[ni][1]);
                    mma_tf32(c[0], c[1], c[2], c[3],
                             alo[mi][0], alo[mi][1], alo[mi][2], alo[mi][3],
                             bhi[ni][0], bhi[ni][1]);
                }
        }

        __syncthreads();
        if (ch + 2 < NCH) load_stage(ch + 2, ch & 1);
        cp_commit();
    }

#pragma unroll
    for (int mi = 0; mi < 4; mi++) {
        int r0 = m0 + wm + mi * 16 + g;
#pragma unroll
        for (int ni = 0; ni < 4; ni++) {
            int cb = n0 + wn + ni * 8 + 2 * tq;
            float2 bia = *(const float2*)&bias[cb];
            float* c = acc[mi][ni];
            *(float2*)&g_xg[(size_t)r0 * G3 + cb] =
                make_float2(c[0] + bia.x, c[1] + bia.y);
            *(float2*)&g_xg[(size_t)(r0 + 8) * G3 + cb] =
                make_float2(c[2] + bia.x, c[3] + bia.y);
        }
    }
}

// ---------------------------------------------------------------------------
// fp32 SGEMM for layer-0 xg (K = 118). (unchanged, passing)
// ---------------------------------------------------------------------------
__global__ __launch_bounds__(256) void gemm_xg_kernel(
    const float* __restrict__ x_in, int K,
    const float* __restrict__ W, const float* __restrict__ bias)
{
    const float* A = x_in;

    __shared__ float As[8][128];
    __shared__ float Bs[8][128];

    const int n0 = blockIdx.x * 128;
    const int m0 = blockIdx.y * 128;
    const int tid = threadIdx.x;
    const int tx = tid & 15;
    const int ty = tid >> 4;

    float acc[8][8];
#pragma unroll
    for (int i = 0; i < 8; i++)
#pragma unroll
        for (int j = 0; j < 8; j++) acc[i][j] = 0.f;

    const int nkt = (K + 7) >> 3;
    for (int kt = 0; kt < nkt; kt++) {
        const int k0 = kt << 3;
#pragma unroll
        for (int i = 0; i < 4; i++) {
            int ii = tid + i * 256;
            int m = ii >> 3, k = ii & 7;
            As[k][m] = (k0 + k < K) ? A[(size_t)(m0 + m) * K + (k0 + k)] : 0.f;
        }
#pragma unroll
        for (int i = 0; i < 4; i++) {
            int ii = tid + i * 256;
            int n = ii >> 3, k = ii & 7;
            Bs[k][n] = (k0 + k < K) ? W[(size_t)(n0 + n) * K + (k0 + k)] : 0.f;
        }
        __syncthreads();
#pragma unroll
        for (int k = 0; k < 8; k++) {
            float a[8], b[8];
#pragma unroll
            for (int i = 0; i < 8; i++) a[i] = As[k][ty * 8 + i];
#pragma unroll
            for (int j = 0; j < 8; j++) b[j] = Bs[k][tx * 8 + j];
#pragma unroll
            for (int i = 0; i < 8; i++)
#pragma unroll
                for (int j = 0; j < 8; j++)
                    acc[i][j] = fmaf(a[i], b[j], acc[i][j]);
        }
        __syncthreads();
    }

#pragma unroll
    for (int i = 0; i < 8; i++) {
        size_t row = (size_t)(m0 + ty * 8 + i) * G3;
#pragma unroll
        for (int j = 0; j < 8; j++) {
            int n = n0 + tx * 8 + j;
            g_xg[row + n] = acc[i][j] + bias[n];
        }
    }
}

// ---------------------------------------------------------------------------
// Final linear: out[b] = dot(h_last[b,:], W_lin) + b_lin
// ---------------------------------------------------------------------------
__global__ __launch_bounds__(256) void final_kernel(
    const float* __restrict__ Wlin, const float* __restrict__ blin,
    float* __restrict__ out)
{
    const int b = blockIdx.x;
    const float* h = g_hb + b * HID;
    float s = 0.f;
    for (int k = threadIdx.x; k < HID; k += 256) s += h[k] * Wlin[k];
#pragma unroll
    for (int o = 16; o > 0; o >>= 1) s += __shfl_down_sync(0xffffffffu, s, o);
    __shared__ float red[8];
    if ((threadIdx.x & 31) == 0) red[threadIdx.x >> 5] = s;
    __syncthreads();
    if (threadIdx.x < 8) {
        s = red[threadIdx.x];
#pragma unroll
        for (int o = 4; o > 0; o >>= 1) s += __shfl_down_sync(0xffu, s, o);
        if (threadIdx.x == 0) out[b] = s + blin[0];
    }
}

// ---------------------------------------------------------------------------
extern "C" void kernel_launch(void* const* d_in, const int* in_sizes, int n_in,
                              void* d_out, int out_size)
{
    const float* x      = (const float*)d_in[0];
    const float* W_ih0  = (const float*)d_in[1];
    const float* W_ih12 = (const float*)d_in[2];
    const float* W_hh   = (const float*)d_in[3];
    const float* b_ih   = (const float*)d_in[4];
    const float* b_hh   = (const float*)d_in[5];
    const float* W_lin  = (const float*)d_in[6];
    const float* b_lin  = (const float*)d_in[7];
    float* out = (float*)d_out;

    cudaFuncSetAttribute(gru_layer_kernel,
                         cudaFuncAttributeMaxDynamicSharedMemorySize, GSM_BYTES);
    const int smem_xg = 2 * XST_F * sizeof(float);
    cudaFuncSetAttribute(gemm_xg_tf32_kernel,
                         cudaFuncAttributeMaxDynamicSharedMemorySize, smem_xg);

    for (int l = 0; l < 3; l++) {
        const int    ysel  = (l == 0) ? 1 : (l == 1 ? 2 : 0);
        const float* Whh_l = W_hh + (size_t)l * G3 * HID;
        const float* bih_l = b_ih + (size_t)l * G3;
        const float* bhh_l = b_hh + (size_t)l * G3;

        if (l == 0) {
            dim3 ggrid(G3 / 128, BT / 128);
            gemm_xg_kernel<<<ggrid, 256>>>(x, DIN0, W_ih0, bih_l);
        } else {
            const float* Wih = W_ih12 + (size_t)(l - 1) * G3 * HID;
            dim3 ggrid(G3 / 64, BT / 128);
            gemm_xg_tf32_kernel<<<ggrid, 128, smem_xg>>>(l, Wih, bih_l);
        }

        gru_layer_kernel<<<NBLK, GNT, GSM_BYTES>>>(Whh_l, bhh_l, ysel);
    }

    final_kernel<<<BATCH, 256>>>(W_lin, b_lin, out);
}

// round 12
// speedup vs baseline: 1.6215x; 1.6215x over previous
#include <cuda_runtime.h>
#include <cuda_bf16.h>
#include <cstdint>

#define HID   1024
#define BATCH 64
#define SEQ   512
#define G3    3072
#define BT    (BATCH * SEQ)
#define DIN0  118

#define NBLK  128          // persistent blocks (all co-resident; <= 148 SMs)
#define GNT   256          // 8 warps: mt = warp&3 (m-tile), wgk = warp>>2 (k-half)
#define GKC   64           // k rows per staged h chunk (each wgk computes 32)
#define GHROW 68           // floats per smem h k-row (64 + 4 pad)
#define NSTG  4            // h ring stages
// smem: W_hi u32[1024][24] (96KB) + h ring 4*64*68*4 (69632) + W_lo u16[1024][24] (48KB)
#define WHI_WORDS (HID * 24)
#define HBUF_FLOATS (GKC * GHROW)
#define SM_WHI_OFF 0
#define SM_HB_OFF  (WHI_WORDS * 4)                         // 98304
#define SM_WLO_OFF (SM_HB_OFF + NSTG * HBUF_FLOATS * 4)    // 167936
#define GSM_BYTES  (SM_WLO_OFF + HID * 24 * 2)             // 217088

// ---------------- scratch (device globals; no allocation allowed) ----------
__device__ float  g_xg[(size_t)BT * G3];      // input projections for current layer
__device__ float  g_yA[(size_t)BT * HID];     // layer outputs ping
__device__ float  g_yB[(size_t)BT * HID];     // layer outputs pong
__device__ float  g_hT[2][HID * BATCH];       // hidden fp32, [k][b], ping-pong
__device__ float  g_hb[BATCH * HID];          // final hidden, batch-major
__device__ unsigned long long g_flags[NBLK * 16];  // per-block step counters (128B stride)

__device__ __forceinline__ float fsigmoid(float x) {
    return 1.f / (1.f + __expf(-x));
}
__device__ __forceinline__ float ftanh(float x) {
    return 2.f / (1.f + __expf(-2.f * x)) - 1.f;
}

// ---------------------------------------------------------------------------
// cp.async / tf32 helpers
// ---------------------------------------------------------------------------
__device__ __forceinline__ void cp_async16(uint32_t smem_dst, const void* gptr) {
    asm volatile("cp.async.cg.shared.global [%0], [%1], 16;\n"
                 :: "r"(smem_dst), "l"(gptr));
}
__device__ __forceinline__ void cp_commit() {
    asm volatile("cp.async.commit_group;\n");
}
template <int N>
__device__ __forceinline__ void cp_wait() {
    asm volatile("cp.async.wait_group %0;\n" :: "n"(N));
}
__device__ __forceinline__ uint32_t f2tf32(float x) {
    uint32_t r;
    asm("cvt.rna.tf32.f32 %0, %1;" : "=r"(r) : "f"(x));
    return r;
}
__device__ __forceinline__ void mma_tf32(
    float& c0, float& c1, float& c2, float& c3,
    uint32_t a0, uint32_t a1, uint32_t a2, uint32_t a3,
    uint32_t b0, uint32_t b1)
{
    asm volatile(
        "mma.sync.aligned.m16n8k8.row.col.f32.tf32.tf32.f32 "
        "{%0,%1,%2,%3}, {%4,%5,%6,%7}, {%8,%9}, {%0,%1,%2,%3};"
        : "+f"(c0), "+f"(c1), "+f"(c2), "+f"(c3)
        : "r"(a0), "r"(a1), "r"(a2), "r"(a3), "r"(b0), "r"(b1));
}

// ---------------------------------------------------------------------------
// Distributed one-hop barrier: producer publishes its per-block flag (release);
// consumer: threads tid<NBLK each poll one flag directly — no central gather,
// no epoch broadcast hop. ONE poll per step, never inside the chunk loop.
// ---------------------------------------------------------------------------
__device__ __forceinline__ void bar_publish(int bid, unsigned long long val) {
    __threadfence();                   // release: order h stores before flag
    __syncthreads();                   // all block threads' writes fenced
    if (threadIdx.x == 0)
        *(volatile unsigned long long*)&g_flags[bid * 16] = val;
}
__device__ __forceinline__ void bar_wait_all(unsigned long long tgt) {
    const int tid = threadIdx.x;
    if (tid < NBLK) {
        while (*(volatile unsigned long long*)&g_flags[tid * 16] < tgt)
            __nanosleep(32);
        __threadfence();               // acquire: order h reads after flags
    }
    __syncthreads();
}

// ---------------------------------------------------------------------------
// Persistent per-layer GRU kernel — tf32x3 mma recurrence (R10 baseline) with
//  * distributed one-hop barrier (per-block flags, direct all-poll)
//  * stage-before-compute chunk ordering (cp.async overlaps the mma work)
// Block i owns HID cols c0..c0+7 (c0=8i) for all 3 gates.
// Warp w: m-tile (w&3), k-half (w>>2) of each 64-row chunk.
// ---------------------------------------------------------------------------
__global__ __launch_bounds__(GNT, 1) void gru_layer_kernel(
    const float* __restrict__ Whh, const float* __restrict__ bhh, int ysel)
{
    extern __shared__ char smraw[];
    uint32_t* W_hi = (uint32_t*)(smraw + SM_WHI_OFF);   // [k*24 + j]
    float*    HBf  = (float*)(smraw + SM_HB_OFF);       // 4 x [64][68]
    uint16_t* W_lo = (uint16_t*)(smraw + SM_WLO_OFF);   // [k*24 + j] bf16 bits

    const int tid  = threadIdx.x;
    const int bid  = blockIdx.x;
    const int c0   = bid * 8;
    const int warp = tid >> 5;
    const int lane = tid & 31;
    const int mt   = warp & 3;                 // m-tile
    const int wgk  = warp >> 2;                // k-half within chunk (0/1)
    const int l4   = lane >> 2;                // 0..7
    const int tq   = lane & 3;                 // 0..3

    // per-launch epoch base: own flag, self-written at each publish; all
    // blocks ended the previous launch with equal values.
    const unsigned long long base =
        *(volatile unsigned long long*)&g_flags[bid * 16];

    // ---- pre-split Whh slice: hi = tf32(w) (u32), lo = bf16(w - hi) ----
    for (int idx = tid; idx < 24 * HID; idx += GNT) {
        int j = idx >> 10;                     // 0..23 = gate*8 + col
        int k = idx & (HID - 1);
        int jg = j >> 3, jc = j & 7;
        float w  = Whh[(size_t)(jg * HID + c0 + jc) * HID + k];
        uint32_t wh = f2tf32(w);
        W_hi[k * 24 + j] = wh;
        __nv_bfloat16 wl = __float2bfloat16(w - __uint_as_float(wh));
        W_lo[k * 24 + j] = *(uint16_t*)&wl;
    }

    // gate constants (used by wg0 only)
    const int cA = c0 + 2 * tq;
    const int bA = mt * 16 + l4;
    float bh[3][2];
#pragma unroll
    for (int gte = 0; gte < 3; gte++) {
        bh[gte][0] = bhh[gte * HID + cA];
        bh[gte][1] = bhh[gte * HID + cA + 1];
    }

    float hp[4] = {0.f, 0.f, 0.f, 0.f};        // h_prev cells (wg0)

    const uint32_t s_hb = (uint32_t)__cvta_generic_to_shared(HBf);
    __syncthreads();                           // W smem ready (block-local)

    for (int t = 0; t < SEQ; t++) {
        // ---- prefetch xg for this step's gate cells (wg0 only) ----
        float xv[3][4];
        if (wgk == 0) {
            const size_t rA = ((size_t)bA * SEQ + t) * G3;
            const size_t rB = ((size_t)(bA + 8) * SEQ + t) * G3;
#pragma unroll
            for (int gte = 0; gte < 3; gte++) {
                xv[gte][0] = __ldcg(&g_xg[rA + gte * HID + cA]);
                xv[gte][1] = __ldcg(&g_xg[rA + gte * HID + cA + 1]);
                xv[gte][2] = __ldcg(&g_xg[rB + gte * HID + cA]);
                xv[gte][3] = __ldcg(&g_xg[rB + gte * HID + cA + 1]);
            }
        }

        float acc[3][4];
#pragma unroll
        for (int nt = 0; nt < 3; nt++)
#pragma unroll
            for (int r = 0; r < 4; r++) acc[nt][r] = 0.f;

        if (t > 0) {
            // ---- ONE distributed barrier per step: h[t] fully published ----
            bar_wait_all(base + (unsigned long long)t);

            const float* hsrc = g_hT[t & 1];

            // prologue: stage chunks 0,1,2 into ring slots 0,1,2
#pragma unroll
            for (int ch = 0; ch < NSTG - 1; ch++) {
                uint32_t dst = s_hb + (uint32_t)ch * (HBUF_FLOATS * 4);
                const float* src = hsrc + (size_t)ch * GKC * BATCH;
#pragma unroll
                for (int j = 0; j < (GKC * 16) / GNT; j++) {   // 4 ops/thread
                    int o = tid + j * GNT;
                    int k = o >> 4, s = o & 15;
                    cp_async16(dst + (uint32_t)(k * GHROW + s * 4) * 4,
                               src + (size_t)k * BATCH + s * 4);
                }
                cp_commit();
            }

#pragma unroll 1
            for (int ch = 0; ch < HID / GKC; ch++) {           // 16 chunks
                cp_wait<NSTG - 2>();           // chunk ch resident
                __syncthreads();               // single sync per chunk

                // stage-before-compute: issue chunk ch+3 NOW so the transfer
                // overlaps this chunk's mma work. Slot (ch+3)&3 == (ch-1)&3,
                // whose readers all passed the sync above.
                if (ch + NSTG - 1 < HID / GKC) {
                    int cn = ch + NSTG - 1;
                    uint32_t dst = s_hb + (uint32_t)(cn & 3) * (HBUF_FLOATS * 4);
                    const float* src = hsrc + (size_t)cn * GKC * BATCH;
#pragma unroll
                    for (int j = 0; j < (GKC * 16) / GNT; j++) {
                        int o = tid + j * GNT;
                        int k = o >> 4, s = o & 15;
                        cp_async16(dst + (uint32_t)(k * GHROW + s * 4) * 4,
                                   src + (size_t)k * BATCH + s * 4);
                    }
                }
                cp_commit();                   // uniform (possibly empty) commit

                const float* hb = HBf + (ch & 3) * HBUF_FLOATS + wgk * 32 * GHROW;
                const int kg = ch * GKC + wgk * 32;

#pragma unroll
                for (int ks = 0; ks < 4; ks++) {
                    const int kk = ks * 8;
                    // A fragments (h fp32 -> hi/lo on the fly)
                    float a0 = hb[(kk + tq) * GHROW + bA];
                    float a1 = hb[(kk + tq) * GHROW + bA + 8];
                    float a2 = hb[(kk + tq + 4) * GHROW + bA];
                    float a3 = hb[(kk + tq + 4) * GHROW + bA + 8];
                    uint32_t ah0 = f2tf32(a0), al0 = f2tf32(a0 - __uint_as_float(ah0));
                    uint32_t ah1 = f2tf32(a1), al1 = f2tf32(a1 - __uint_as_float(ah1));
                    uint32_t ah2 = f2tf32(a2), al2 = f2tf32(a2 - __uint_as_float(ah2));
                    uint32_t ah3 = f2tf32(a3), al3 = f2tf32(a3 - __uint_as_float(ah3));
#pragma unroll
                    for (int nt = 0; nt < 3; nt++) {
                        int j = nt * 8 + l4;
                        int w0 = (kg + kk + tq) * 24 + j;
                        int w1 = (kg + kk + tq + 4) * 24 + j;
                        uint32_t bh0 = W_hi[w0];
                        uint32_t bh1 = W_hi[w1];
                        uint32_t bl0 = ((uint32_t)W_lo[w0]) << 16;
                        uint32_t bl1 = ((uint32_t)W_lo[w1]) << 16;
                        float* c = acc[nt];
                        mma_tf32(c[0], c[1], c[2], c[3], ah0, ah1, ah2, ah3, bh0, bh1);
                        mma_tf32(c[0], c[1], c[2], c[3], ah0, ah1, ah2, ah3, bl0, bl1);
                        mma_tf32(c[0], c[1], c[2], c[3], al0, al1, al2, al3, bh0, bh1);
                    }
                }
            }

            // ---- cross-warpgroup acc reduction (reuse h ring as scratch) ----
            cp_wait<0>();
            __syncthreads();
            float* red = HBf;                  // 128 threads x 12 floats
            if (wgk == 1) {
                int o = (mt * 32 + lane) * 12;
#pragma unroll
                for (int nt = 0; nt < 3; nt++)
#pragma unroll
                    for (int r = 0; r < 4; r++)
                        red[o + nt * 4 + r] = acc[nt][r];
            }
            __syncthreads();
            if (wgk == 0) {
                int o = (mt * 32 + lane) * 12;
#pragma unroll
                for (int nt = 0; nt < 3; nt++)
#pragma unroll
                    for (int r = 0; r < 4; r++)
                        acc[nt][r] += red[o + nt * 4 + r];
            }
        }

        // ---- gates, in register (wg0 only) ----
        if (wgk == 0) {
            float* hdst = g_hT[(t + 1) & 1];
#pragma unroll
            for (int r = 0; r < 4; r++) {
                int i  = r >> 1, jj = r & 1;
                int b  = bA + 8 * i;
                int cc = cA + jj;
                int ar = 2 * i + jj;
                float rg = fsigmoid(xv[0][2 * i + jj] + acc[0][ar] + bh[0][jj]);
                float zg = fsigmoid(xv[1][2 * i + jj] + acc[1][ar] + bh[1][jj]);
                float ng = ftanh(xv[2][2 * i + jj] + rg * (acc[2][ar] + bh[2][jj]));
                float h  = (1.f - zg) * ng + zg * hp[r];
                hp[r] = h;

                hdst[(size_t)cc * BATCH + b] = h;

                size_t bt = (size_t)b * SEQ + t;
                if (ysel == 1)      g_yA[bt * HID + cc] = h;
                else if (ysel == 2) g_yB[bt * HID + cc] = h;
                if (t == SEQ - 1)   g_hb[(size_t)b * HID + cc] = h;
            }
        }

        // publish step completion (h[t+1] visible): one flag store per block.
        bar_publish(bid, base + (unsigned long long)(t + 1));
    }
}

// ---------------------------------------------------------------------------
// tf32 split-3 MMA GEMM for xg of layers 1,2 (K = 1024). (unchanged, passing)
// ---------------------------------------------------------------------------
#define XKC   32
#define XLD   36
#define XA_F  (128 * XLD)
#define XB_F  (64 * XLD)
#define XST_F (XA_F + XB_F)

__global__ __launch_bounds__(128, 2) void gemm_xg_tf32_kernel(
    int a_sel, const float* __restrict__ W, const float* __restrict__ bias)
{
    const float* A = (a_sel == 1) ? g_yA : g_yB;
    const int K = HID;

    extern __shared__ float xs[];
    const int tid  = threadIdx.x;
    const int warp = tid >> 5;
    const int lane = tid & 31;
    const int g    = lane >> 2;
    const int tq   = lane & 3;

    const int n0 = blockIdx.x * 64;
    const int m0 = blockIdx.y * 128;
    const int wm = (warp & 1) * 64;
    const int wn = (warp >> 1) * 32;

    const uint32_t s_base = (uint32_t)__cvta_generic_to_shared(xs);

    float acc[4][4][4];
#pragma unroll
    for (int mi = 0; mi < 4; mi++)
#pragma unroll
        for (int ni = 0; ni < 4; ni++)
#pragma unroll
            for (int r = 0; r < 4; r++) acc[mi][ni][r] = 0.f;

    auto load_stage = [&](int ch, int buf) {
        const int k0 = ch * XKC;
        uint32_t dstA = s_base + (uint32_t)buf * XST_F * 4;
        uint32_t dstB = dstA + XA_F * 4;
#pragma unroll
        for (int j = 0; j < 8; j++) {
            int o = tid + j * 128;
            int row = o >> 3, seg = o & 7;
            cp_async16(dstA + (uint32_t)(row * XLD + seg * 4) * 4,
                       A + (size_t)(m0 + row) * K + k0 + seg * 4);
        }
#pragma unroll
        for (int j = 0; j < 4; j++) {
            int o = tid + j * 128;
            int row = o >> 3, seg = o & 7;
            cp_async16(dstB + (uint32_t)(row * XLD + seg * 4) * 4,
                       W + (size_t)(n0 + row) * K + k0 + seg * 4);
        }
    };

    const int NCH = K / XKC;
    load_stage(0, 0); cp_commit();
    load_stage(1, 1); cp_commit();

    for (int ch = 0; ch < NCH; ch++) {
        cp_wait<1>();
        __syncthreads();
        const float* As = xs + (ch & 1) * XST_F;
        const float* Bs = As + XA_F;

#pragma unroll
        for (int ks = 0; ks < 4; ks++) {
            const int k = ks * 8;
            uint32_t ahi[4][4], alo[4][4];
#pragma unroll
            for (int mi = 0; mi < 4; mi++) {
                int rbase = wm + mi * 16 + g;
                float r0 = As[(rbase)     * XLD + k + tq];
                float r1 = As[(rbase + 8) * XLD + k + tq];
                float r2 = As[(rbase)     * XLD + k + tq + 4];
                float r3 = As[(rbase + 8) * XLD + k + tq + 4];
                ahi[mi][0] = f2tf32(r0); alo[mi][0] = f2tf32(r0 - __uint_as_float(ahi[mi][0]));
                ahi[mi][1] = f2tf32(r1); alo[mi][1] = f2tf32(r1 - __uint_as_float(ahi[mi][1]));
                ahi[mi][2] = f2tf32(r2); alo[mi][2] = f2tf32(r2 - __uint_as_float(ahi[mi][2]));
                ahi[mi][3] = f2tf32(r3); alo[mi][3] = f2tf32(r3 - __uint_as_float(ahi[mi][3]));
            }
            uint32_t bhi[4][2], blo[4][2];
#pragma unroll
            for (int ni = 0; ni < 4; ni++) {
                int nbase = wn + ni * 8 + g;
                float r0 = Bs[nbase * XLD + k + tq];
                float r1 = Bs[nbase * XLD + k + tq + 4];
                bhi[ni][0] = f2tf32(r0); blo[ni][0] = f2tf32(r0 - __uint_as_float(bhi[ni][0]));
                bhi[ni][1] = f2tf32(r1); blo[ni][1] = f2tf32(r1 - __uint_as_float(bhi[ni][1]));
            }
#pragma unroll
            for (int mi = 0; mi < 4; mi++)
#pragma unroll
                for (int ni = 0; ni < 4; ni++) {
                    float* c = acc[mi][ni];
                    mma_tf32(c[0], c[1], c[2], c[3],
                             ahi[mi][0], ahi[mi][1], ahi[mi][2], ahi[mi][3],
                             bhi[ni][0], bhi[ni][1]);
                    mma_tf32(c[0], c[1], c[2], c[3],
                             ahi[mi][0], ahi[mi][1], ahi[mi][2], ahi[mi][3],
                             blo[ni][0], blo[ni][1]);
                    mma_tf32(c[0], c[1], c[2], c[3],
                             alo[mi][0], alo[mi][1], alo[mi][2], alo[mi][3],
                             bhi[ni][0], bhi[ni][1]);
                }
        }

        __syncthreads();
        if (ch + 2 < NCH) load_stage(ch + 2, ch & 1);
        cp_commit();
    }

#pragma unroll
    for (int mi = 0; mi < 4; mi++) {
        int r0 = m0 + wm + mi * 16 + g;
#pragma unroll
        for (int ni = 0; ni < 4; ni++) {
            int cb = n0 + wn + ni * 8 + 2 * tq;
            float2 bia = *(const float2*)&bias[cb];
            float* c = acc[mi][ni];
            *(float2*)&g_xg[(size_t)r0 * G3 + cb] =
                make_float2(c[0] + bia.x, c[1] + bia.y);
            *(float2*)&g_xg[(size_t)(r0 + 8) * G3 + cb] =
                make_float2(c[2] + bia.x, c[3] + bia.y);
        }
    }
}

// ---------------------------------------------------------------------------
// fp32 SGEMM for layer-0 xg (K = 118). (unchanged, passing)
// ---------------------------------------------------------------------------
__global__ __launch_bounds__(256) void gemm_xg_kernel(
    const float* __restrict__ x_in, int K,
    const float* __restrict__ W, const float* __restrict__ bias)
{
    const float* A = x_in;

    __shared__ float As[8][128];
    __shared__ float Bs[8][128];

    const int n0 = blockIdx.x * 128;
    const int m0 = blockIdx.y * 128;
    const int tid = threadIdx.x;
    const int tx = tid & 15;
    const int ty = tid >> 4;

    float acc[8][8];
#pragma unroll
    for (int i = 0; i < 8; i++)
#pragma unroll
        for (int j = 0; j < 8; j++) acc[i][j] = 0.f;

    const int nkt = (K + 7) >> 3;
    for (int kt = 0; kt < nkt; kt++) {
        const int k0 = kt << 3;
#pragma unroll
        for (int i = 0; i < 4; i++) {
            int ii = tid + i * 256;
            int m = ii >> 3, k = ii & 7;
            As[k][m] = (k0 + k < K) ? A[(size_t)(m0 + m) * K + (k0 + k)] : 0.f;
        }
#pragma unroll
        for (int i = 0; i < 4; i++) {
            int ii = tid + i * 256;
            int n = ii >> 3, k = ii & 7;
            Bs[k][n] = (k0 + k < K) ? W[(size_t)(n0 + n) * K + (k0 + k)] : 0.f;
        }
        __syncthreads();
#pragma unroll
        for (int k = 0; k < 8; k++) {
            float a[8], b[8];
#pragma unroll
            for (int i = 0; i < 8; i++) a[i] = As[k][ty * 8 + i];
#pragma unroll
            for (int j = 0; j < 8; j++) b[j] = Bs[k][tx * 8 + j];
#pragma unroll
            for (int i = 0; i < 8; i++)
#pragma unroll
                for (int j = 0; j < 8; j++)
                    acc[i][j] = fmaf(a[i], b[j], acc[i][j]);
        }
        __syncthreads();
    }

#pragma unroll
    for (int i = 0; i < 8; i++) {
        size_t row = (size_t)(m0 + ty * 8 + i) * G3;
#pragma unroll
        for (int j = 0; j < 8; j++) {
            int n = n0 + tx * 8 + j;
            g_xg[row + n] = acc[i][j] + bias[n];
        }
    }
}

// ---------------------------------------------------------------------------
// Final linear: out[b] = dot(h_last[b,:], W_lin) + b_lin
// ---------------------------------------------------------------------------
__global__ __launch_bounds__(256) void final_kernel(
    const float* __restrict__ Wlin, const float* __restrict__ blin,
    float* __restrict__ out)
{
    const int b = blockIdx.x;
    const float* h = g_hb + b * HID;
    float s = 0.f;
    for (int k = threadIdx.x; k < HID; k += 256) s += h[k] * Wlin[k];
#pragma unroll
    for (int o = 16; o > 0; o >>= 1) s += __shfl_down_sync(0xffffffffu, s, o);
    __shared__ float red[8];
    if ((threadIdx.x & 31) == 0) red[threadIdx.x >> 5] = s;
    __syncthreads();
    if (threadIdx.x < 8) {
        s = red[threadIdx.x];
#pragma unroll
        for (int o = 4; o > 0; o >>= 1) s += __shfl_down_sync(0xffu, s, o);
        if (threadIdx.x == 0) out[b] = s + blin[0];
    }
}

// ---------------------------------------------------------------------------
extern "C" void kernel_launch(void* const* d_in, const int* in_sizes, int n_in,
                              void* d_out, int out_size)
{
    const float* x      = (const float*)d_in[0];
    const float* W_ih0  = (const float*)d_in[1];
    const float* W_ih12 = (const float*)d_in[2];
    const float* W_hh   = (const float*)d_in[3];
    const float* b_ih   = (const float*)d_in[4];
    const float* b_hh   = (const float*)d_in[5];
    const float* W_lin  = (const float*)d_in[6];
    const float* b_lin  = (const float*)d_in[7];
    float* out = (float*)d_out;

    cudaFuncSetAttribute(gru_layer_kernel,
                         cudaFuncAttributeMaxDynamicSharedMemorySize, GSM_BYTES);
    const int smem_xg = 2 * XST_F * sizeof(float);
    cudaFuncSetAttribute(gemm_xg_tf32_kernel,
                         cudaFuncAttributeMaxDynamicSharedMemorySize, smem_xg);

    for (int l = 0; l < 3; l++) {
        const int    ysel  = (l == 0) ? 1 : (l == 1 ? 2 : 0);
        const float* Whh_l = W_hh + (size_t)l * G3 * HID;
        const float* bih_l = b_ih + (size_t)l * G3;
        const float* bhh_l = b_hh + (size_t)l * G3;

        if (l == 0) {
            dim3 ggrid(G3 / 128, BT / 128);
            gemm_xg_kernel<<<ggrid, 256>>>(x, DIN0, W_ih0, bih_l);
        } else {
            const float* Wih = W_ih12 + (size_t)(l - 1) * G3 * HID;
            dim3 ggrid(G3 / 64, BT / 128);
            gemm_xg_tf32_kernel<<<ggrid, 128, smem_xg>>>(l, Wih, bih_l);
        }

        gru_layer_kernel<<<NBLK, GNT, GSM_BYTES>>>(Whh_l, bhh_l, ysel);
    }

    final_kernel<<<BATCH, 256>>>(W_lin, b_lin, out);
}

// round 13
// speedup vs baseline: 2.0653x; 1.2736x over previous
#include <cuda_runtime.h>
#include <cuda_bf16.h>
#include <cstdint>

#define HID   1024
#define BATCH 64
#define SEQ   512
#define G3    3072
#define BT    (BATCH * SEQ)
#define DIN0  118

#define NBLK  128          // persistent blocks (all co-resident; <= 148 SMs)
#define GNT   256          // 8 warps: mt = warp&3 (m-tile), wgk = warp>>2 (k-half)
#define GKC   64           // k rows per staged h chunk (32 u32 pairs)
#define NSTG  4            // h ring stages
#define HROW  36           // u32 per smem h row (32 data + 4 pad; 16B-aligned rows)
#define WROW  516          // u32 per smem W row (512 data + 4 pad; conflict-free)
// smem layout (bytes)
#define SM_WBH_OFF 0
#define SM_WBL_OFF (24 * WROW * 4)                     // 49536
#define SM_HB_OFF  (2 * 24 * WROW * 4)                 // 99072
#define HSTG_BYTES (2 * BATCH * HROW * 4)              // 18432 (hi + lo)
#define GSM_BYTES  (SM_HB_OFF + NSTG * HSTG_BYTES)     // 172800

// ---------------- scratch (device globals; no allocation allowed) ----------
__device__ float    g_xg[(size_t)BT * G3];    // input projections for current layer
__device__ float    g_yA[(size_t)BT * HID];   // layer outputs ping
__device__ float    g_yB[(size_t)BT * HID];   // layer outputs pong
__device__ uint32_t g_h2hi[2][BATCH * 512];   // h bf16-hi pairs [b][kpair], ping-pong
__device__ uint32_t g_h2lo[2][BATCH * 512];   // h bf16-lo residual pairs
__device__ float    g_hb[BATCH * HID];        // final hidden, batch-major
__device__ unsigned long long g_flags[NBLK * 16];  // per-block step counters (128B stride)

__device__ __forceinline__ float fsigmoid(float x) {
    return 1.f / (1.f + __expf(-x));
}
__device__ __forceinline__ float ftanh(float x) {
    return 2.f / (1.f + __expf(-2.f * x)) - 1.f;
}
__device__ __forceinline__ uint16_t bfbits(float x) {
    __nv_bfloat16 b = __float2bfloat16(x);
    return *(uint16_t*)&b;
}
__device__ __forceinline__ float bf2f(uint16_t u) {
    __nv_bfloat16 b = *(__nv_bfloat16*)&u;
    return __bfloat162float(b);
}

// ---------------------------------------------------------------------------
// cp.async / mma helpers
// ---------------------------------------------------------------------------
__device__ __forceinline__ void cp_async16(uint32_t smem_dst, const void* gptr) {
    asm volatile("cp.async.cg.shared.global [%0], [%1], 16;\n"
                 :: "r"(smem_dst), "l"(gptr));
}
__device__ __forceinline__ void cp_commit() {
    asm volatile("cp.async.commit_group;\n");
}
template <int N>
__device__ __forceinline__ void cp_wait() {
    asm volatile("cp.async.wait_group %0;\n" :: "n"(N));
}
__device__ __forceinline__ uint32_t f2tf32(float x) {
    uint32_t r;
    asm("cvt.rna.tf32.f32 %0, %1;" : "=r"(r) : "f"(x));
    return r;
}
__device__ __forceinline__ void mma_bf16(
    float& c0, float& c1, float& c2, float& c3,
    uint32_t a0, uint32_t a1, uint32_t a2, uint32_t a3,
    uint32_t b0, uint32_t b1)
{
    asm volatile(
        "mma.sync.aligned.m16n8k16.row.col.f32.bf16.bf16.f32 "
        "{%0,%1,%2,%3}, {%4,%5,%6,%7}, {%8,%9}, {%0,%1,%2,%3};"
        : "+f"(c0), "+f"(c1), "+f"(c2), "+f"(c3)
        : "r"(a0), "r"(a1), "r"(a2), "r"(a3), "r"(b0), "r"(b1));
}
__device__ __forceinline__ void mma_tf32(
    float& c0, float& c1, float& c2, float& c3,
    uint32_t a0, uint32_t a1, uint32_t a2, uint32_t a3,
    uint32_t b0, uint32_t b1)
{
    asm volatile(
        "mma.sync.aligned.m16n8k8.row.col.f32.tf32.tf32.f32 "
        "{%0,%1,%2,%3}, {%4,%5,%6,%7}, {%8,%9}, {%0,%1,%2,%3};"
        : "+f"(c0), "+f"(c1), "+f"(c2), "+f"(c3)
        : "r"(a0), "r"(a1), "r"(a2), "r"(a3), "r"(b0), "r"(b1));
}

// ---------------------------------------------------------------------------
// Distributed one-hop barrier (proven R12). ONE poll per step.
// ---------------------------------------------------------------------------
__device__ __forceinline__ void bar_publish(int bid, unsigned long long val) {
    __threadfence();
    __syncthreads();
    if (threadIdx.x == 0)
        *(volatile unsigned long long*)&g_flags[bid * 16] = val;
}
__device__ __forceinline__ void bar_wait_all(unsigned long long tgt) {
    const int tid = threadIdx.x;
    if (tid < NBLK) {
        while (*(volatile unsigned long long*)&g_flags[tid * 16] < tgt)
            __nanosleep(32);
        __threadfence();
    }
    __syncthreads();
}

// ---------------------------------------------------------------------------
// Persistent per-layer GRU kernel — bf16 m16n8k16 3-split (hh + hl + lh).
// Block i owns HID cols c0..c0+7 (c0=8i) for all 3 gates.
//   smem: WB_hi/WB_lo [j=0..23][512 u32 kpairs] (99 KB, resident)
//         h ring: 4 x { HA_hi[64][36 u32], HA_lo[64][36 u32] } (73.7 KB)
// Warp w: m-tile (w&3) [batches 16(w&3)..+15], k-half (w>>2) of each chunk.
// h stored as packed bf16 pairs (hi + residual lo): A frags are raw LDS.32,
// NO per-iteration conversions. One distributed barrier per step.
// ---------------------------------------------------------------------------
__global__ __launch_bounds__(GNT, 1) void gru_layer_kernel(
    const float* __restrict__ Whh, const float* __restrict__ bhh, int ysel)
{
    extern __shared__ char smraw[];
    uint32_t* WBh = (uint32_t*)(smraw + SM_WBH_OFF);   // [j*WROW + kpair]
    uint32_t* WBl = (uint32_t*)(smraw + SM_WBL_OFF);

    const int tid  = threadIdx.x;
    const int bid  = blockIdx.x;
    const int c0   = bid * 8;
    const int warp = tid >> 5;
    const int lane = tid & 31;
    const int mt   = warp & 3;                 // m-tile
    const int wgk  = warp >> 2;                // k-half within chunk (0/1)
    const int l4   = lane >> 2;                // 0..7
    const int tq   = lane & 3;                 // 0..3

    const unsigned long long base =
        *(volatile unsigned long long*)&g_flags[bid * 16];

    // ---- pre-split Whh slice into bf16 hi/lo k-pairs (once) ----
    // j = gate*8 + col; value rows (gate*HID + c0+col) of Whh, k-major pairs.
    for (int idx = tid; idx < 24 * 512; idx += GNT) {
        int j  = idx >> 9;                     // 0..23
        int kp = idx & 511;
        int jg = j >> 3, jc = j & 7;
        const float* wr = Whh + (size_t)(jg * HID + c0 + jc) * HID;
        float w0 = wr[2 * kp], w1 = wr[2 * kp + 1];
        uint16_t h0 = bfbits(w0), h1 = bfbits(w1);
        WBh[j * WROW + kp] = ((uint32_t)h1 << 16) | h0;
        uint16_t l0 = bfbits(w0 - bf2f(h0)), l1 = bfbits(w1 - bf2f(h1));
        WBl[j * WROW + kp] = ((uint32_t)l1 << 16) | l0;
    }

    // gate constants (used by wg0 only)
    const int cA = c0 + 2 * tq;
    const int bA = mt * 16 + l4;
    float bh[3][2];
#pragma unroll
    for (int gte = 0; gte < 3; gte++) {
        bh[gte][0] = bhh[gte * HID + cA];
        bh[gte][1] = bhh[gte * HID + cA + 1];
    }

    float hp[4] = {0.f, 0.f, 0.f, 0.f};        // h_prev cells (wg0)

    const uint32_t s_hb = (uint32_t)__cvta_generic_to_shared(smraw + SM_HB_OFF);
    __syncthreads();                           // W smem ready (block-local)

    for (int t = 0; t < SEQ; t++) {
        // ---- prefetch xg for this step's gate cells (wg0 only) ----
        float xv[3][4];
        if (wgk == 0) {
            const size_t rA = ((size_t)bA * SEQ + t) * G3;
            const size_t rB = ((size_t)(bA + 8) * SEQ + t) * G3;
#pragma unroll
            for (int gte = 0; gte < 3; gte++) {
                xv[gte][0] = __ldcg(&g_xg[rA + gte * HID + cA]);
                xv[gte][1] = __ldcg(&g_xg[rA + gte * HID + cA + 1]);
                xv[gte][2] = __ldcg(&g_xg[rB + gte * HID + cA]);
                xv[gte][3] = __ldcg(&g_xg[rB + gte * HID + cA + 1]);
            }
        }

        float acc[3][4];
#pragma unroll
        for (int nt = 0; nt < 3; nt++)
#pragma unroll
            for (int r = 0; r < 4; r++) acc[nt][r] = 0.f;

        if (t > 0) {
            bar_wait_all(base + (unsigned long long)t);

            const uint32_t* hhi = g_h2hi[t & 1];
            const uint32_t* hlo = g_h2lo[t & 1];

            // stage loader: chunk ch -> ring slot; hi then lo (1024 segs, 4/thr)
            auto stage = [&](int ch) {
                uint32_t dst = s_hb + (uint32_t)(ch & 3) * HSTG_BYTES;
#pragma unroll
                for (int jj = 0; jj < 4; jj++) {
                    int o   = tid + jj * GNT;
                    int arr = o >> 9;            // 0 = hi, 1 = lo
                    int oo  = o & 511;
                    int b   = oo >> 3, s = oo & 7;
                    const uint32_t* src =
                        (arr ? hlo : hhi) + (size_t)b * 512 + ch * 32 + s * 4;
                    cp_async16(dst + (uint32_t)(arr * (BATCH * HROW) +
                                                b * HROW + s * 4) * 4, src);
                }
                cp_commit();
            };

            // prologue: stage chunks 0,1,2
#pragma unroll
            for (int ch = 0; ch < NSTG - 1; ch++) stage(ch);

#pragma unroll 1
            for (int ch = 0; ch < HID / GKC; ch++) {           // 16 chunks
                cp_wait<NSTG - 2>();           // chunk ch resident
                __syncthreads();

                // stage-before-compute: chunk ch+3 overlaps this chunk's mma
                if (ch + NSTG - 1 < HID / GKC) stage(ch + NSTG - 1);
                else cp_commit();              // keep wait_group math uniform

                const uint32_t* HAh = (const uint32_t*)(smraw + SM_HB_OFF) +
                                      (ch & 3) * (2 * BATCH * HROW);
                const uint32_t* HAl = HAh + BATCH * HROW;

#pragma unroll
                for (int ks = 0; ks < 2; ks++) {
                    const int ko = wgk * 16 + ks * 8;          // u32 index in row
                    // A fragments: raw LDS.32, no conversions
                    uint32_t ah0 = HAh[bA * HROW + ko + tq];
                    uint32_t ah1 = HAh[(bA + 8) * HROW + ko + tq];
                    uint32_t ah2 = HAh[bA * HROW + ko + tq + 4];
                    uint32_t ah3 = HAh[(bA + 8) * HROW + ko + tq + 4];
                    uint32_t al0 = HAl[bA * HROW + ko + tq];
                    uint32_t al1 = HAl[(bA + 8) * HROW + ko + tq];
                    uint32_t al2 = HAl[bA * HROW + ko + tq + 4];
                    uint32_t al3 = HAl[(bA + 8) * HROW + ko + tq + 4];
                    const int kb = ch * 32 + ko + tq;          // u32 index in W row
#pragma unroll
                    for (int nt = 0; nt < 3; nt++) {
                        int j = nt * 8 + l4;
                        uint32_t bh0 = WBh[j * WROW + kb];
                        uint32_t bh1 = WBh[j * WROW + kb + 4];
                        uint32_t bl0 = WBl[j * WROW + kb];
                        uint32_t bl1 = WBl[j * WROW + kb + 4];
                        float* c = acc[nt];
                        mma_bf16(c[0], c[1], c[2], c[3], ah0, ah1, ah2, ah3, bh0, bh1);
                        mma_bf16(c[0], c[1], c[2], c[3], ah0, ah1, ah2, ah3, bl0, bl1);
                        mma_bf16(c[0], c[1], c[2], c[3], al0, al1, al2, al3, bh0, bh1);
                    }
                }
            }

            // ---- cross-warpgroup acc reduction (reuse h ring as scratch) ----
            cp_wait<0>();
            __syncthreads();
            float* red = (float*)(smraw + SM_HB_OFF);   // 128 thr x 12 floats
            if (wgk == 1) {
                int o = (mt * 32 + lane) * 12;
#pragma unroll
                for (int nt = 0; nt < 3; nt++)
#pragma unroll
                    for (int r = 0; r < 4; r++)
                        red[o + nt * 4 + r] = acc[nt][r];
            }
            __syncthreads();
            if (wgk == 0) {
                int o = (mt * 32 + lane) * 12;
#pragma unroll
                for (int nt = 0; nt < 3; nt++)
#pragma unroll
                    for (int r = 0; r < 4; r++)
                        acc[nt][r] += red[o + nt * 4 + r];
            }
        }

        // ---- gates, in register (wg0 only) ----
        if (wgk == 0) {
            const int slot = (t + 1) & 1;
            const int kp   = 4 * bid + tq;     // packed pair column index
            float hcell[2][2];
#pragma unroll
            for (int r = 0; r < 4; r++) {
                int i  = r >> 1, jj = r & 1;
                int ar = 2 * i + jj;
                float rg = fsigmoid(xv[0][ar] + acc[0][ar] + bh[0][jj]);
                float zg = fsigmoid(xv[1][ar] + acc[1][ar] + bh[1][jj]);
                float ng = ftanh(xv[2][ar] + rg * (acc[2][ar] + bh[2][jj]));
                float h  = (1.f - zg) * ng + zg * hp[r];
                hp[r] = h;
                hcell[i][jj] = h;
            }
#pragma unroll
            for (int i = 0; i < 2; i++) {
                int b = bA + 8 * i;
                float h0 = hcell[i][0], h1 = hcell[i][1];
                uint16_t u0 = bfbits(h0), u1 = bfbits(h1);
                g_h2hi[slot][(size_t)b * 512 + kp] = ((uint32_t)u1 << 16) | u0;
                uint16_t v0 = bfbits(h0 - bf2f(u0)), v1 = bfbits(h1 - bf2f(u1));
                g_h2lo[slot][(size_t)b * 512 + kp] = ((uint32_t)v1 << 16) | v0;

                size_t bt = (size_t)b * SEQ + t;
                if (ysel == 1) {
                    g_yA[bt * HID + cA]     = h0;
                    g_yA[bt * HID + cA + 1] = h1;
                } else if (ysel == 2) {
                    g_yB[bt * HID + cA]     = h0;
                    g_yB[bt * HID + cA + 1] = h1;
                }
                if (t == SEQ - 1) {
                    g_hb[(size_t)b * HID + cA]     = h0;
                    g_hb[(size_t)b * HID + cA + 1] = h1;
                }
            }
        }

        bar_publish(bid, base + (unsigned long long)(t + 1));
    }
}

// ---------------------------------------------------------------------------
// tf32 split-3 MMA GEMM for xg of layers 1,2 (K = 1024). (unchanged, passing)
// ---------------------------------------------------------------------------
#define XKC   32
#define XLD   36
#define XA_F  (128 * XLD)
#define XB_F  (64 * XLD)
#define XST_F (XA_F + XB_F)

__global__ __launch_bounds__(128, 2) void gemm_xg_tf32_kernel(
    int a_sel, const float* __restrict__ W, const float* __restrict__ bias)
{
    const float* A = (a_sel == 1) ? g_yA : g_yB;
    const int K = HID;

    extern __shared__ float xs[];
    const int tid  = threadIdx.x;
    const int warp = tid >> 5;
    const int lane = tid & 31;
    const int g    = lane >> 2;
    const int tq   = lane & 3;

    const int n0 = blockIdx.x * 64;
    const int m0 = blockIdx.y * 128;
    const int wm = (warp & 1) * 64;
    const int wn = (warp >> 1) * 32;

    const uint32_t s_base = (uint32_t)__cvta_generic_to_shared(xs);

    float acc[4][4][4];
#pragma unroll
    for (int mi = 0; mi < 4; mi++)
#pragma unroll
        for (int ni = 0; ni < 4; ni++)
#pragma unroll
            for (int r = 0; r < 4; r++) acc[mi][ni][r] = 0.f;

    auto load_stage = [&](int ch, int buf) {
        const int k0 = ch * XKC;
        uint32_t dstA = s_base + (uint32_t)buf * XST_F * 4;
        uint32_t dstB = dstA + XA_F * 4;
#pragma unroll
        for (int j = 0; j < 8; j++) {
            int o = tid + j * 128;
            int row = o >> 3, seg = o & 7;
            cp_async16(dstA + (uint32_t)(row * XLD + seg * 4) * 4,
                       A + (size_t)(m0 + row) * K + k0 + seg * 4);
        }
#pragma unroll
        for (int j = 0; j < 4; j++) {
            int o = tid + j * 128;
            int row = o >> 3, seg = o & 7;
            cp_async16(dstB + (uint32_t)(row * XLD + seg * 4) * 4,
                       W + (size_t)(n0 + row) * K + k0 + seg * 4);
        }
    };

    const int NCH = K / XKC;
    load_stage(0, 0); cp_commit();
    load_stage(1, 1); cp_commit();

    for (int ch = 0; ch < NCH; ch++) {
        cp_wait<1>();
        __syncthreads();
        const float* As = xs + (ch & 1) * XST_F;
        const float* Bs = As + XA_F;

#pragma unroll
        for (int ks = 0; ks < 4; ks++) {
            const int k = ks * 8;
            uint32_t ahi[4][4], alo[4][4];
#pragma unroll
            for (int mi = 0; mi < 4; mi++) {
                int rbase = wm + mi * 16 + g;
                float r0 = As[(rbase)     * XLD + k + tq];
                float r1 = As[(rbase + 8) * XLD + k + tq];
                float r2 = As[(rbase)     * XLD + k + tq + 4];
                float r3 = As[(rbase + 8) * XLD + k + tq + 4];
                ahi[mi][0] = f2tf32(r0); alo[mi][0] = f2tf32(r0 - __uint_as_float(ahi[mi][0]));
                ahi[mi][1] = f2tf32(r1); alo[mi][1] = f2tf32(r1 - __uint_as_float(ahi[mi][1]));
                ahi[mi][2] = f2tf32(r2); alo[mi][2] = f2tf32(r2 - __uint_as_float(ahi[mi][2]));
                ahi[mi][3] = f2tf32(r3); alo[mi][3] = f2tf32(r3 - __uint_as_float(ahi[mi][3]));
            }
            uint32_t bhi[4][2], blo[4][2];
#pragma unroll
            for (int ni = 0; ni < 4; ni++) {
                int nbase = wn + ni * 8 + g;
                float r0 = Bs[nbase * XLD + k + tq];
                float r1 = Bs[nbase * XLD + k + tq + 4];
                bhi[ni][0] = f2tf32(r0); blo[ni][0] = f2tf32(r0 - __uint_as_float(bhi[ni][0]));
                bhi[ni][1] = f2tf32(r1); blo[ni][1] = f2tf32(r1 - __uint_as_float(bhi[ni][1]));
            }
#pragma unroll
            for (int mi = 0; mi < 4; mi++)
#pragma unroll
                for (int ni = 0; ni < 4; ni++) {
                    float* c = acc[mi][ni];
                    mma_tf32(c[0], c[1], c[2], c[3],
                             ahi[mi][0], ahi[mi][1], ahi[mi][2], ahi[mi][3],
                             bhi[ni][0], bhi[ni][1]);
                    mma_tf32(c[0], c[1], c[2], c[3],
                             ahi[mi][0], ahi[mi][1], ahi[mi][2], ahi[mi][3],
                             blo[ni][0], blo[ni][1]);
                    mma_tf32(c[0], c[1], c[2], c[3],
                             alo[mi][0], alo[mi][1], alo[mi][2], alo[mi][3],
                             bhi[ni][0], bhi[ni][1]);
                }
        }

        __syncthreads();
        if (ch + 2 < NCH) load_stage(ch + 2, ch & 1);
        cp_commit();
    }

#pragma unroll
    for (int mi = 0; mi < 4; mi++) {
        int r0 = m0 + wm + mi * 16 + g;
#pragma unroll
        for (int ni = 0; ni < 4; ni++) {
            int cb = n0 + wn + ni * 8 + 2 * tq;
            float2 bia = *(const float2*)&bias[cb];
            float* c = acc[mi][ni];
            *(float2*)&g_xg[(size_t)r0 * G3 + cb] =
                make_float2(c[0] + bia.x, c[1] + bia.y);
            *(float2*)&g_xg[(size_t)(r0 + 8) * G3 + cb] =
                make_float2(c[2] + bia.x, c[3] + bia.y);
        }
    }
}

// ---------------------------------------------------------------------------
// fp32 SGEMM for layer-0 xg (K = 118). (unchanged, passing)
// ---------------------------------------------------------------------------
__global__ __launch_bounds__(256) void gemm_xg_kernel(
    const float* __restrict__ x_in, int K,
    const float* __restrict__ W, const float* __restrict__ bias)
{
    const float* A = x_in;

    __shared__ float As[8][128];
    __shared__ float Bs[8][128];

    const int n0 = blockIdx.x * 128;
    const int m0 = blockIdx.y * 128;
    const int tid = threadIdx.x;
    const int tx = tid & 15;
    const int ty = tid >> 4;

    float acc[8][8];
#pragma unroll
    for (int i = 0; i < 8; i++)
#pragma unroll
        for (int j = 0; j < 8; j++) acc[i][j] = 0.f;

    const int nkt = (K + 7) >> 3;
    for (int kt = 0; kt < nkt; kt++) {
        const int k0 = kt << 3;
#pragma unroll
        for (int i = 0; i < 4; i++) {
            int ii = tid + i * 256;
            int m = ii >> 3, k = ii & 7;
            As[k][m] = (k0 + k < K) ? A[(size_t)(m0 + m) * K + (k0 + k)] : 0.f;
        }
#pragma unroll
        for (int i = 0; i < 4; i++) {
            int ii = tid + i * 256;
            int n = ii >> 3, k = ii & 7;
            Bs[k][n] = (k0 + k < K) ? W[(size_t)(n0 + n) * K + (k0 + k)] : 0.f;
        }
        __syncthreads();
#pragma unroll
        for (int k = 0; k < 8; k++) {
            float a[8], b[8];
#pragma unroll
            for (int i = 0; i < 8; i++) a[i] = As[k][ty * 8 + i];
#pragma unroll
            for (int j = 0; j < 8; j++) b[j] = Bs[k][tx * 8 + j];
#pragma unroll
            for (int i = 0; i < 8; i++)
#pragma unroll
                for (int j = 0; j < 8; j++)
                    acc[i][j] = fmaf(a[i], b[j], acc[i][j]);
        }
        __syncthreads();
    }

#pragma unroll
    for (int i = 0; i < 8; i++) {
        size_t row = (size_t)(m0 + ty * 8 + i) * G3;
#pragma unroll
        for (int j = 0; j < 8; j++) {
            int n = n0 + tx * 8 + j;
            g_xg[row + n] = acc[i][j] + bias[n];
        }
    }
}

// ---------------------------------------------------------------------------
// Final linear: out[b] = dot(h_last[b,:], W_lin) + b_lin
// ---------------------------------------------------------------------------
__global__ __launch_bounds__(256) void final_kernel(
    const float* __restrict__ Wlin, const float* __restrict__ blin,
    float* __restrict__ out)
{
    const int b = blockIdx.x;
    const float* h = g_hb + b * HID;
    float s = 0.f;
    for (int k = threadIdx.x; k < HID; k += 256) s += h[k] * Wlin[k];
#pragma unroll
    for (int o = 16; o > 0; o >>= 1) s += __shfl_down_sync(0xffffffffu, s, o);
    __shared__ float red[8];
    if ((threadIdx.x & 31) == 0) red[threadIdx.x >> 5] = s;
    __syncthreads();
    if (threadIdx.x < 8) {
        s = red[threadIdx.x];
#pragma unroll
        for (int o = 4; o > 0; o >>= 1) s += __shfl_down_sync(0xffu, s, o);
        if (threadIdx.x == 0) out[b] = s + blin[0];
    }
}

// ---------------------------------------------------------------------------
extern "C" void kernel_launch(void* const* d_in, const int* in_sizes, int n_in,
                              void* d_out, int out_size)
{
    const float* x      = (const float*)d_in[0];
    const float* W_ih0  = (const float*)d_in[1];
    const float* W_ih12 = (const float*)d_in[2];
    const float* W_hh   = (const float*)d_in[3];
    const float* b_ih   = (const float*)d_in[4];
    const float* b_hh   = (const float*)d_in[5];
    const float* W_lin  = (const float*)d_in[6];
    const float* b_lin  = (const float*)d_in[7];
    float* out = (float*)d_out;

    cudaFuncSetAttribute(gru_layer_kernel,
                         cudaFuncAttributeMaxDynamicSharedMemorySize, GSM_BYTES);
    const int smem_xg = 2 * XST_F * sizeof(float);
    cudaFuncSetAttribute(gemm_xg_tf32_kernel,
                         cudaFuncAttributeMaxDynamicSharedMemorySize, smem_xg);

    for (int l = 0; l < 3; l++) {
        const int    ysel  = (l == 0) ? 1 : (l == 1 ? 2 : 0);
        const float* Whh_l = W_hh + (size_t)l * G3 * HID;
        const float* bih_l = b_ih + (size_t)l * G3;
        const float* bhh_l = b_hh + (size_t)l * G3;

        if (l == 0) {
            dim3 ggrid(G3 / 128, BT / 128);
            gemm_xg_kernel<<<ggrid, 256>>>(x, DIN0, W_ih0, bih_l);
        } else {
            const float* Wih = W_ih12 + (size_t)(l - 1) * G3 * HID;
            dim3 ggrid(G3 / 64, BT / 128);
            gemm_xg_tf32_kernel<<<ggrid, 128, smem_xg>>>(l, Wih, bih_l);
        }

        gru_layer_kernel<<<NBLK, GNT, GSM_BYTES>>>(Whh_l, bhh_l, ysel);
    }

    final_kernel<<<BATCH, 256>>>(W_lin, b_lin, out);
}

// round 14
// speedup vs baseline: 2.1104x; 1.0218x over previous
#include <cuda_runtime.h>
#include <cuda_bf16.h>
#include <cstdint>

#define HID   1024
#define BATCH 64
#define SEQ   512
#define G3    3072
#define BT    (BATCH * SEQ)
#define DIN0  118

#define NBLK  128          // persistent blocks (all co-resident; <= 148 SMs)
#define GNT   256          // 8 warps: mt = warp&3 (m-tile), wgk = warp>>2 (k-half)
#define NCH   16           // h chunks per step (64 k-rows = 32 u32 pairs each)
#define NSTG  6            // per-warp ring stages
#define SROW  20           // u32 per stage row (16 data + 4 pad; conflict-free)
#define STG_U32 (32 * SROW)            // 640 u32 = 2560 B per stage (16 hi + 16 lo rows)
#define WROW  516                      // u32 per smem W row (512 + 4 pad)
#define SM_WBH_OFF 0
#define SM_WBL_OFF (24 * WROW * 4)                     // 49536
#define SM_ST_OFF  (2 * 24 * WROW * 4)                 // 99072
#define GSM_BYTES  (SM_ST_OFF + 8 * NSTG * STG_U32 * 4)  // 99072+122880 = 221952

// ---------------- scratch (device globals; no allocation allowed) ----------
__device__ float    g_xg[(size_t)BT * G3];    // input projections for current layer
__device__ float    g_yA[(size_t)BT * HID];   // layer outputs ping
__device__ float    g_yB[(size_t)BT * HID];   // layer outputs pong
__device__ uint32_t g_h2hi[2][BATCH * 512];   // h bf16-hi pairs [b][kpair], ping-pong
__device__ uint32_t g_h2lo[2][BATCH * 512];   // h bf16-lo residual pairs
__device__ float    g_hb[BATCH * HID];        // final hidden, batch-major
__device__ unsigned long long g_flags[NBLK * 16];  // per-block step counters (128B stride)

__device__ __forceinline__ float fsigmoid(float x) {
    return 1.f / (1.f + __expf(-x));
}
__device__ __forceinline__ float ftanh(float x) {
    return 2.f / (1.f + __expf(-2.f * x)) - 1.f;
}
__device__ __forceinline__ uint16_t bfbits(float x) {
    __nv_bfloat16 b = __float2bfloat16(x);
    return *(uint16_t*)&b;
}
__device__ __forceinline__ float bf2f(uint16_t u) {
    __nv_bfloat16 b = *(__nv_bfloat16*)&u;
    return __bfloat162float(b);
}

// ---------------------------------------------------------------------------
// cp.async / mma helpers
// ---------------------------------------------------------------------------
__device__ __forceinline__ void cp_async16(uint32_t smem_dst, const void* gptr) {
    asm volatile("cp.async.cg.shared.global [%0], [%1], 16;\n"
                 :: "r"(smem_dst), "l"(gptr));
}
__device__ __forceinline__ void cp_commit() {
    asm volatile("cp.async.commit_group;\n");
}
template <int N>
__device__ __forceinline__ void cp_wait() {
    asm volatile("cp.async.wait_group %0;\n" :: "n"(N));
}
__device__ __forceinline__ uint32_t f2tf32(float x) {
    uint32_t r;
    asm("cvt.rna.tf32.f32 %0, %1;" : "=r"(r) : "f"(x));
    return r;
}
__device__ __forceinline__ void mma_bf16(
    float& c0, float& c1, float& c2, float& c3,
    uint32_t a0, uint32_t a1, uint32_t a2, uint32_t a3,
    uint32_t b0, uint32_t b1)
{
    asm volatile(
        "mma.sync.aligned.m16n8k16.row.col.f32.bf16.bf16.f32 "
        "{%0,%1,%2,%3}, {%4,%5,%6,%7}, {%8,%9}, {%0,%1,%2,%3};"
        : "+f"(c0), "+f"(c1), "+f"(c2), "+f"(c3)
        : "r"(a0), "r"(a1), "r"(a2), "r"(a3), "r"(b0), "r"(b1));
}
__device__ __forceinline__ void mma_tf32(
    float& c0, float& c1, float& c2, float& c3,
    uint32_t a0, uint32_t a1, uint32_t a2, uint32_t a3,
    uint32_t b0, uint32_t b1)
{
    asm volatile(
        "mma.sync.aligned.m16n8k8.row.col.f32.tf32.tf32.f32 "
        "{%0,%1,%2,%3}, {%4,%5,%6,%7}, {%8,%9}, {%0,%1,%2,%3};"
        : "+f"(c0), "+f"(c1), "+f"(c2), "+f"(c3)
        : "r"(a0), "r"(a1), "r"(a2), "r"(a3), "r"(b0), "r"(b1));
}

// ---------------------------------------------------------------------------
// Distributed one-hop barrier (proven R12/R13). ONE poll per step.
// ---------------------------------------------------------------------------
__device__ __forceinline__ void bar_publish(int bid, unsigned long long val) {
    __threadfence();
    __syncthreads();
    if (threadIdx.x == 0)
        *(volatile unsigned long long*)&g_flags[bid * 16] = val;
}
__device__ __forceinline__ void bar_wait_all(unsigned long long tgt) {
    const int tid = threadIdx.x;
    if (tid < NBLK) {
        while (*(volatile unsigned long long*)&g_flags[tid * 16] < tgt)
            __nanosleep(32);
        __threadfence();
    }
    __syncthreads();
}

// ---------------------------------------------------------------------------
// Persistent per-layer GRU kernel — bf16 m16n8k16 3-split with WARP-PRIVATE
// h staging: each warp cp.asyncs only the 16-batch x 16-u32 subtile it reads,
// into its own 6-deep smem ring. Chunk loop: cp.async.wait + __syncwarp ONLY
// (zero block syncs in the hot loop). Block syncs remain at the reduction.
// Block i owns HID cols c0..c0+7 for all 3 gates; warp (mt,wgk): m-tile mt,
// k-half wgk.
// ---------------------------------------------------------------------------
__global__ __launch_bounds__(GNT, 1) void gru_layer_kernel(
    const float* __restrict__ Whh, const float* __restrict__ bhh, int ysel)
{
    extern __shared__ char smraw[];
    uint32_t* WBh = (uint32_t*)(smraw + SM_WBH_OFF);   // [j*WROW + kpair]
    uint32_t* WBl = (uint32_t*)(smraw + SM_WBL_OFF);

    const int tid  = threadIdx.x;
    const int bid  = blockIdx.x;
    const int c0   = bid * 8;
    const int warp = tid >> 5;
    const int lane = tid & 31;
    const int mt   = warp & 3;                 // m-tile
    const int wgk  = warp >> 2;                // k-half within chunk (0/1)
    const int l4   = lane >> 2;                // 0..7
    const int tq   = lane & 3;                 // 0..3

    const unsigned long long base =
        *(volatile unsigned long long*)&g_flags[bid * 16];

    // ---- pre-split Whh slice into bf16 hi/lo k-pairs (once) ----
    for (int idx = tid; idx < 24 * 512; idx += GNT) {
        int j  = idx >> 9;                     // 0..23 = gate*8 + col
        int kp = idx & 511;
        int jg = j >> 3, jc = j & 7;
        const float* wr = Whh + (size_t)(jg * HID + c0 + jc) * HID;
        float w0 = wr[2 * kp], w1 = wr[2 * kp + 1];
        uint16_t h0 = bfbits(w0), h1 = bfbits(w1);
        WBh[j * WROW + kp] = ((uint32_t)h1 << 16) | h0;
        uint16_t l0 = bfbits(w0 - bf2f(h0)), l1 = bfbits(w1 - bf2f(h1));
        WBl[j * WROW + kp] = ((uint32_t)l1 << 16) | l0;
    }

    // gate constants (used by wg0 only)
    const int cA = c0 + 2 * tq;
    const int bA = mt * 16 + l4;
    float bh[3][2];
#pragma unroll
    for (int gte = 0; gte < 3; gte++) {
        bh[gte][0] = bhh[gte * HID + cA];
        bh[gte][1] = bhh[gte * HID + cA + 1];
    }

    float hp[4] = {0.f, 0.f, 0.f, 0.f};        // h_prev cells (wg0)

    // per-warp stage ring base (smem)
    uint32_t* WST = (uint32_t*)(smraw + SM_ST_OFF) + warp * NSTG * STG_U32;
    const uint32_t s_wst =
        (uint32_t)__cvta_generic_to_shared(WST);

    // per-lane staging decomposition: 4 segs/lane, seg e = lane + 32*j
    //   arr = e>>6 (0=hi,1=lo), b = (e>>2)&15, s = e&3 (16B seg within 16 u32)
    __syncthreads();                           // W smem ready (block-local)

    for (int t = 0; t < SEQ; t++) {
        // ---- prefetch xg for this step's gate cells (wg0 only) ----
        float xv[3][4];
        if (wgk == 0) {
            const size_t rA = ((size_t)bA * SEQ + t) * G3;
            const size_t rB = ((size_t)(bA + 8) * SEQ + t) * G3;
#pragma unroll
            for (int gte = 0; gte < 3; gte++) {
                xv[gte][0] = __ldcg(&g_xg[rA + gte * HID + cA]);
                xv[gte][1] = __ldcg(&g_xg[rA + gte * HID + cA + 1]);
                xv[gte][2] = __ldcg(&g_xg[rB + gte * HID + cA]);
                xv[gte][3] = __ldcg(&g_xg[rB + gte * HID + cA + 1]);
            }
        }

        float acc[3][4];
#pragma unroll
        for (int nt = 0; nt < 3; nt++)
#pragma unroll
            for (int r = 0; r < 4; r++) acc[nt][r] = 0.f;

        if (t > 0) {
            bar_wait_all(base + (unsigned long long)t);

            const uint32_t* hhi = g_h2hi[t & 1];
            const uint32_t* hlo = g_h2lo[t & 1];

            // per-warp stage: warp (mt,wgk) loads batches 16mt..16mt+15,
            // kpairs ch*32 + wgk*16 .. +16 (hi rows 0-15, lo rows 16-31).
            auto stage = [&](int ch) {
                uint32_t dst = s_wst + (uint32_t)(ch % NSTG) * (STG_U32 * 4);
#pragma unroll
                for (int j = 0; j < 4; j++) {
                    int e   = lane + 32 * j;
                    int arr = e >> 6;
                    int b   = (e >> 2) & 15;
                    int s   = e & 3;
                    const uint32_t* src =
                        (arr ? hlo : hhi) +
                        (size_t)(mt * 16 + b) * 512 + ch * 32 + wgk * 16 + s * 4;
                    cp_async16(dst + (uint32_t)((arr * 16 + b) * SROW + s * 4) * 4,
                               src);
                }
                cp_commit();
            };

            // prologue: stage chunks 0..4 (ring depth 6, 5 in flight)
#pragma unroll
            for (int ch = 0; ch < NSTG - 1; ch++) stage(ch);

#pragma unroll 1
            for (int ch = 0; ch < NCH; ch++) {
                cp_wait<NSTG - 2>();           // chunk ch resident (per-lane)
                __syncwarp();                  // warp-local only!

                if (ch + NSTG - 1 < NCH) stage(ch + NSTG - 1);
                else cp_commit();              // keep wait_group math uniform

                const uint32_t* HA = WST + (ch % NSTG) * STG_U32;
#pragma unroll
                for (int ks = 0; ks < 2; ks++) {
                    const int ko = ks * 8;
                    // A fragments: warp-private rows (local batch = l4, l4+8)
                    uint32_t ah0 = HA[l4 * SROW + ko + tq];
                    uint32_t ah1 = HA[(l4 + 8) * SROW + ko + tq];
                    uint32_t ah2 = HA[l4 * SROW + ko + tq + 4];
                    uint32_t ah3 = HA[(l4 + 8) * SROW + ko + tq + 4];
                    uint32_t al0 = HA[(16 + l4) * SROW + ko + tq];
                    uint32_t al1 = HA[(24 + l4) * SROW + ko + tq];
                    uint32_t al2 = HA[(16 + l4) * SROW + ko + tq + 4];
                    uint32_t al3 = HA[(24 + l4) * SROW + ko + tq + 4];
                    const int kb = ch * 32 + wgk * 16 + ks * 8 + tq;
#pragma unroll
                    for (int nt = 0; nt < 3; nt++) {
                        int j = nt * 8 + l4;
                        uint32_t bh0 = WBh[j * WROW + kb];
                        uint32_t bh1 = WBh[j * WROW + kb + 4];
                        uint32_t bl0 = WBl[j * WROW + kb];
                        uint32_t bl1 = WBl[j * WROW + kb + 4];
                        float* c = acc[nt];
                        mma_bf16(c[0], c[1], c[2], c[3], ah0, ah1, ah2, ah3, bh0, bh1);
                        mma_bf16(c[0], c[1], c[2], c[3], ah0, ah1, ah2, ah3, bl0, bl1);
                        mma_bf16(c[0], c[1], c[2], c[3], al0, al1, al2, al3, bh0, bh1);
                    }
                }
            }

            // ---- cross-warpgroup acc reduction (reuse stage area) ----
            cp_wait<0>();
            __syncthreads();
            float* red = (float*)(smraw + SM_ST_OFF);   // 128 thr x 12 floats
            if (wgk == 1) {
                int o = (mt * 32 + lane) * 12;
#pragma unroll
                for (int nt = 0; nt < 3; nt++)
#pragma unroll
                    for (int r = 0; r < 4; r++)
                        red[o + nt * 4 + r] = acc[nt][r];
            }
            __syncthreads();
            if (wgk == 0) {
                int o = (mt * 32 + lane) * 12;
#pragma unroll
                for (int nt = 0; nt < 3; nt++)
#pragma unroll
                    for (int r = 0; r < 4; r++)
                        acc[nt][r] += red[o + nt * 4 + r];
            }
        }

        // ---- gates, in register (wg0 only) ----
        if (wgk == 0) {
            const int slot = (t + 1) & 1;
            const int kp   = 4 * bid + tq;     // packed pair column index
            float hcell[2][2];
#pragma unroll
            for (int r = 0; r < 4; r++) {
                int i  = r >> 1, jj = r & 1;
                int ar = 2 * i + jj;
                float rg = fsigmoid(xv[0][ar] + acc[0][ar] + bh[0][jj]);
                float zg = fsigmoid(xv[1][ar] + acc[1][ar] + bh[1][jj]);
                float ng = ftanh(xv[2][ar] + rg * (acc[2][ar] + bh[2][jj]));
                float h  = (1.f - zg) * ng + zg * hp[r];
                hp[r] = h;
                hcell[i][jj] = h;
            }
#pragma unroll
            for (int i = 0; i < 2; i++) {
                int b = bA + 8 * i;
                float h0 = hcell[i][0], h1 = hcell[i][1];
                uint16_t u0 = bfbits(h0), u1 = bfbits(h1);
                g_h2hi[slot][(size_t)b * 512 + kp] = ((uint32_t)u1 << 16) | u0;
                uint16_t v0 = bfbits(h0 - bf2f(u0)), v1 = bfbits(h1 - bf2f(u1));
                g_h2lo[slot][(size_t)b * 512 + kp] = ((uint32_t)v1 << 16) | v0;

                size_t bt = (size_t)b * SEQ + t;
                if (ysel == 1) {
                    g_yA[bt * HID + cA]     = h0;
                    g_yA[bt * HID + cA + 1] = h1;
                } else if (ysel == 2) {
                    g_yB[bt * HID + cA]     = h0;
                    g_yB[bt * HID + cA + 1] = h1;
                }
                if (t == SEQ - 1) {
                    g_hb[(size_t)b * HID + cA]     = h0;
                    g_hb[(size_t)b * HID + cA + 1] = h1;
                }
            }
        }

        bar_publish(bid, base + (unsigned long long)(t + 1));
    }
}

// ---------------------------------------------------------------------------
// tf32 split-3 MMA GEMM for xg of layers 1,2 (K = 1024). (unchanged, passing)
// ---------------------------------------------------------------------------
#define XKC   32
#define XLD   36
#define XA_F  (128 * XLD)
#define XB_F  (64 * XLD)
#define XST_F (XA_F + XB_F)

__global__ __launch_bounds__(128, 2) void gemm_xg_tf32_kernel(
    int a_sel, const float* __restrict__ W, const float* __restrict__ bias)
{
    const float* A = (a_sel == 1) ? g_yA : g_yB;
    const int K = HID;

    extern __shared__ float xs[];
    const int tid  = threadIdx.x;
    const int warp = tid >> 5;
    const int lane = tid & 31;
    const int g    = lane >> 2;
    const int tq   = lane & 3;

    const int n0 = blockIdx.x * 64;
    const int m0 = blockIdx.y * 128;
    const int wm = (warp & 1) * 64;
    const int wn = (warp >> 1) * 32;

    const uint32_t s_base = (uint32_t)__cvta_generic_to_shared(xs);

    float acc[4][4][4];
#pragma unroll
    for (int mi = 0; mi < 4; mi++)
#pragma unroll
        for (int ni = 0; ni < 4; ni++)
#pragma unroll
            for (int r = 0; r < 4; r++) acc[mi][ni][r] = 0.f;

    auto load_stage = [&](int ch, int buf) {
        const int k0 = ch * XKC;
        uint32_t dstA = s_base + (uint32_t)buf * XST_F * 4;
        uint32_t dstB = dstA + XA_F * 4;
#pragma unroll
        for (int j = 0; j < 8; j++) {
            int o = tid + j * 128;
            int row = o >> 3, seg = o & 7;
            cp_async16(dstA + (uint32_t)(row * XLD + seg * 4) * 4,
                       A + (size_t)(m0 + row) * K + k0 + seg * 4);
        }
#pragma unroll
        for (int j = 0; j < 4; j++) {
            int o = tid + j * 128;
            int row = o >> 3, seg = o & 7;
            cp_async16(dstB + (uint32_t)(row * XLD + seg * 4) * 4,
                       W + (size_t)(n0 + row) * K + k0 + seg * 4);
        }
    };

    const int NXC = K / XKC;
    load_stage(0, 0); cp_commit();
    load_stage(1, 1); cp_commit();

    for (int ch = 0; ch < NXC; ch++) {
        cp_wait<1>();
        __syncthreads();
        const float* As = xs + (ch & 1) * XST_F;
        const float* Bs = As + XA_F;

#pragma unroll
        for (int ks = 0; ks < 4; ks++) {
            const int k = ks * 8;
            uint32_t ahi[4][4], alo[4][4];
#pragma unroll
            for (int mi = 0; mi < 4; mi++) {
                int rbase = wm + mi * 16 + g;
                float r0 = As[(rbase)     * XLD + k + tq];
                float r1 = As[(rbase + 8) * XLD + k + tq];
                float r2 = As[(rbase)     * XLD + k + tq + 4];
                float r3 = As[(rbase + 8) * XLD + k + tq + 4];
                ahi[mi][0] = f2tf32(r0); alo[mi][0] = f2tf32(r0 - __uint_as_float(ahi[mi][0]));
                ahi[mi][1] = f2tf32(r1); alo[mi][1] = f2tf32(r1 - __uint_as_float(ahi[mi][1]));
                ahi[mi][2] = f2tf32(r2); alo[mi][2] = f2tf32(r2 - __uint_as_float(ahi[mi][2]));
                ahi[mi][3] = f2tf32(r3); alo[mi][3] = f2tf32(r3 - __uint_as_float(ahi[mi][3]));
            }
            uint32_t bhi[4][2], blo[4][2];
#pragma unroll
            for (int ni = 0; ni < 4; ni++) {
                int nbase = wn + ni * 8 + g;
                float r0 = Bs[nbase * XLD + k + tq];
                float r1 = Bs[nbase * XLD + k + tq + 4];
                bhi[ni][0] = f2tf32(r0); blo[ni][0] = f2tf32(r0 - __uint_as_float(bhi[ni][0]));
                bhi[ni][1] = f2tf32(r1); blo[ni][1] = f2tf32(r1 - __uint_as_float(bhi[ni][1]));
            }
#pragma unroll
            for (int mi = 0; mi < 4; mi++)
#pragma unroll
                for (int ni = 0; ni < 4; ni++) {
                    float* c = acc[mi][ni];
                    mma_tf32(c[0], c[1], c[2], c[3],
                             ahi[mi][0], ahi[mi][1], ahi[mi][2], ahi[mi][3],
                             bhi[ni][0], bhi[ni][1]);
                    mma_tf32(c[0], c[1], c[2], c[3],
                             ahi[mi][0], ahi[mi][1], ahi[mi][2], ahi[mi][3],
                             blo[ni][0], blo[ni][1]);
                    mma_tf32(c[0], c[1], c[2], c[3],
                             alo[mi][0], alo[mi][1], alo[mi][2], alo[mi][3],
                             bhi[ni][0], bhi[ni][1]);
                }
        }

        __syncthreads();
        if (ch + 2 < NXC) load_stage(ch + 2, ch & 1);
        cp_commit();
    }

#pragma unroll
    for (int mi = 0; mi < 4; mi++) {
        int r0 = m0 + wm + mi * 16 + g;
#pragma unroll
        for (int ni = 0; ni < 4; ni++) {
            int cb = n0 + wn + ni * 8 + 2 * tq;
            float2 bia = *(const float2*)&bias[cb];
            float* c = acc[mi][ni];
            *(float2*)&g_xg[(size_t)r0 * G3 + cb] =
                make_float2(c[0] + bia.x, c[1] + bia.y);
            *(float2*)&g_xg[(size_t)(r0 + 8) * G3 + cb] =
                make_float2(c[2] + bia.x, c[3] + bia.y);
        }
    }
}

// ---------------------------------------------------------------------------
// fp32 SGEMM for layer-0 xg (K = 118). (unchanged, passing)
// ---------------------------------------------------------------------------
__global__ __launch_bounds__(256) void gemm_xg_kernel(
    const float* __restrict__ x_in, int K,
    const float* __restrict__ W, const float* __restrict__ bias)
{
    const float* A = x_in;

    __shared__ float As[8][128];
    __shared__ float Bs[8][128];

    const int n0 = blockIdx.x * 128;
    const int m0 = blockIdx.y * 128;
    const int tid = threadIdx.x;
    const int tx = tid & 15;
    const int ty = tid >> 4;

    float acc[8][8];
#pragma unroll
    for (int i = 0; i < 8; i++)
#pragma unroll
        for (int j = 0; j < 8; j++) acc[i][j] = 0.f;

    const int nkt = (K + 7) >> 3;
    for (int kt = 0; kt < nkt; kt++) {
        const int k0 = kt << 3;
#pragma unroll
        for (int i = 0; i < 4; i++) {
            int ii = tid + i * 256;
            int m = ii >> 3, k = ii & 7;
            As[k][m] = (k0 + k < K) ? A[(size_t)(m0 + m) * K + (k0 + k)] : 0.f;
        }
#pragma unroll
        for (int i = 0; i < 4; i++) {
            int ii = tid + i * 256;
            int n = ii >> 3, k = ii & 7;
            Bs[k][n] = (k0 + k < K) ? W[(size_t)(n0 + n) * K + (k0 + k)] : 0.f;
        }
        __syncthreads();
#pragma unroll
        for (int k = 0; k < 8; k++) {
            float a[8], b[8];
#pragma unroll
            for (int i = 0; i < 8; i++) a[i] = As[k][ty * 8 + i];
#pragma unroll
            for (int j = 0; j < 8; j++) b[j] = Bs[k][tx * 8 + j];
#pragma unroll
            for (int i = 0; i < 8; i++)
#pragma unroll
                for (int j = 0; j < 8; j++)
                    acc[i][j] = fmaf(a[i], b[j], acc[i][j]);
        }
        __syncthreads();
    }

#pragma unroll
    for (int i = 0; i < 8; i++) {
        size_t row = (size_t)(m0 + ty * 8 + i) * G3;
#pragma unroll
        for (int j = 0; j < 8; j++) {
            int n = n0 + tx * 8 + j;
            g_xg[row + n] = acc[i][j] + bias[n];
        }
    }
}

// ---------------------------------------------------------------------------
// Final linear: out[b] = dot(h_last[b,:], W_lin) + b_lin
// ---------------------------------------------------------------------------
__global__ __launch_bounds__(256) void final_kernel(
    const float* __restrict__ Wlin, const float* __restrict__ blin,
    float* __restrict__ out)
{
    const int b = blockIdx.x;
    const float* h = g_hb + b * HID;
    float s = 0.f;
    for (int k = threadIdx.x; k < HID; k += 256) s += h[k] * Wlin[k];
#pragma unroll
    for (int o = 16; o > 0; o >>= 1) s += __shfl_down_sync(0xffffffffu, s, o);
    __shared__ float red[8];
    if ((threadIdx.x & 31) == 0) red[threadIdx.x >> 5] = s;
    __syncthreads();
    if (threadIdx.x < 8) {
        s = red[threadIdx.x];
#pragma unroll
        for (int o = 4; o > 0; o >>= 1) s += __shfl_down_sync(0xffu, s, o);
        if (threadIdx.x == 0) out[b] = s + blin[0];
    }
}

// ---------------------------------------------------------------------------
extern "C" void kernel_launch(void* const* d_in, const int* in_sizes, int n_in,
                              void* d_out, int out_size)
{
    const float* x      = (const float*)d_in[0];
    const float* W_ih0  = (const float*)d_in[1];
    const float* W_ih12 = (const float*)d_in[2];
    const float* W_hh   = (const float*)d_in[3];
    const float* b_ih   = (const float*)d_in[4];
    const float* b_hh   = (const float*)d_in[5];
    const float* W_lin  = (const float*)d_in[6];
    const float* b_lin  = (const float*)d_in[7];
    float* out = (float*)d_out;

    cudaFuncSetAttribute(gru_layer_kernel,
                         cudaFuncAttributeMaxDynamicSharedMemorySize, GSM_BYTES);
    const int smem_xg = 2 * XST_F * sizeof(float);
    cudaFuncSetAttribute(gemm_xg_tf32_kernel,
                         cudaFuncAttributeMaxDynamicSharedMemorySize, smem_xg);

    for (int l = 0; l < 3; l++) {
        const int    ysel  = (l == 0) ? 1 : (l == 1 ? 2 : 0);
        const float* Whh_l = W_hh + (size_t)l * G3 * HID;
        const float* bih_l = b_ih + (size_t)l * G3;
        const float* bhh_l = b_hh + (size_t)l * G3;

        if (l == 0) {
            dim3 ggrid(G3 / 128, BT / 128);
            gemm_xg_kernel<<<ggrid, 256>>>(x, DIN0, W_ih0, bih_l);
        } else {
            const float* Wih = W_ih12 + (size_t)(l - 1) * G3 * HID;
            dim3 ggrid(G3 / 64, BT / 128);
            gemm_xg_tf32_kernel<<<ggrid, 128, smem_xg>>>(l, Wih, bih_l);
        }

        gru_layer_kernel<<<NBLK, GNT, GSM_BYTES>>>(Whh_l, bhh_l, ysel);
    }

    final_kernel<<<BATCH, 256>>>(W_lin, b_lin, out);
}

// round 15
// speedup vs baseline: 2.3112x; 1.0952x over previous
#include <cuda_runtime.h>
#include <cuda_bf16.h>
#include <cstdint>

#define HID   1024
#define BATCH 64
#define SEQ   512
#define G3    3072
#define BT    (BATCH * SEQ)
#define DIN0  118
#define NKP   512          // packed k-pairs per row (HID/2)

#define NBLK  128          // persistent blocks (all co-resident; <= 148 SMs)
#define GNT   256          // 8 warps: mt = warp&3 (m-tile), wgk = warp>>2 (k-half)
#define NCH   16           // h chunks per step (64 k-rows = 32 u32 pairs each)
#define NSTG  6            // per-warp ring stages
#define SROW  20           // u32 per stage row (16 data + 4 pad; conflict-free)
#define STG_U32 (32 * SROW)            // 640 u32 per stage (16 hi + 16 lo rows)
#define WROW  516                      // u32 per smem W row (512 + 4 pad)
#define SM_WBH_OFF 0
#define SM_WBL_OFF (24 * WROW * 4)                     // 49536
#define SM_ST_OFF  (2 * 24 * WROW * 4)                 // 99072
#define GSM_BYTES  (SM_ST_OFF + 8 * NSTG * STG_U32 * 4)  // 221952

// ---------------- scratch (device globals; no allocation allowed) ----------
__device__ float    g_xg[(size_t)BT * G3];    // input projections for current layer
__device__ uint32_t g_y2hi[2][(size_t)BT * NKP];  // layer outputs, packed bf16-hi pairs
__device__ uint32_t g_y2lo[2][(size_t)BT * NKP];  // packed bf16 residual pairs
__device__ uint32_t g_wih2hi[2][(size_t)G3 * NKP]; // W_ih12 packed bf16-hi
__device__ uint32_t g_wih2lo[2][(size_t)G3 * NKP]; // W_ih12 packed bf16-lo
__device__ uint32_t g_h2hi[2][BATCH * NKP];   // h bf16-hi pairs [b][kpair], ping-pong
__device__ uint32_t g_h2lo[2][BATCH * NKP];   // h bf16-lo residual pairs
__device__ float    g_hb[BATCH * HID];        // final hidden, batch-major
__device__ unsigned long long g_flags[NBLK * 16];  // per-block step counters

__device__ __forceinline__ float fsigmoid(float x) {
    return 1.f / (1.f + __expf(-x));
}
__device__ __forceinline__ float ftanh(float x) {
    return 2.f / (1.f + __expf(-2.f * x)) - 1.f;
}
__device__ __forceinline__ uint16_t bfbits(float x) {
    __nv_bfloat16 b = __float2bfloat16(x);
    return *(uint16_t*)&b;
}
__device__ __forceinline__ float bf2f(uint16_t u) {
    __nv_bfloat16 b = *(__nv_bfloat16*)&u;
    return __bfloat162float(b);
}

// ---------------------------------------------------------------------------
// cp.async / mma helpers
// ---------------------------------------------------------------------------
__device__ __forceinline__ void cp_async16(uint32_t smem_dst, const void* gptr) {
    asm volatile("cp.async.cg.shared.global [%0], [%1], 16;\n"
                 :: "r"(smem_dst), "l"(gptr));
}
__device__ __forceinline__ void cp_commit() {
    asm volatile("cp.async.commit_group;\n");
}
template <int N>
__device__ __forceinline__ void cp_wait() {
    asm volatile("cp.async.wait_group %0;\n" :: "n"(N));
}
__device__ __forceinline__ void mma_bf16(
    float& c0, float& c1, float& c2, float& c3,
    uint32_t a0, uint32_t a1, uint32_t a2, uint32_t a3,
    uint32_t b0, uint32_t b1)
{
    asm volatile(
        "mma.sync.aligned.m16n8k16.row.col.f32.bf16.bf16.f32 "
        "{%0,%1,%2,%3}, {%4,%5,%6,%7}, {%8,%9}, {%0,%1,%2,%3};"
        : "+f"(c0), "+f"(c1), "+f"(c2), "+f"(c3)
        : "r"(a0), "r"(a1), "r"(a2), "r"(a3), "r"(b0), "r"(b1));
}

// ---------------------------------------------------------------------------
// Distributed one-hop barrier (proven R12-R14). ONE poll per step.
// ---------------------------------------------------------------------------
__device__ __forceinline__ void bar_publish(int bid, unsigned long long val) {
    __threadfence();
    __syncthreads();
    if (threadIdx.x == 0)
        *(volatile unsigned long long*)&g_flags[bid * 16] = val;
}
__device__ __forceinline__ void bar_wait_all(unsigned long long tgt) {
    const int tid = threadIdx.x;
    if (tid < NBLK) {
        while (*(volatile unsigned long long*)&g_flags[tid * 16] < tgt)
            __nanosleep(32);
        __threadfence();
    }
    __syncthreads();
}

// ---------------------------------------------------------------------------
// Persistent per-layer GRU kernel (R14 topology, unchanged except y writes:
// y now emitted as packed bf16 hi/lo pairs, reusing the h2 pack registers).
// ---------------------------------------------------------------------------
__global__ __launch_bounds__(GNT, 1) void gru_layer_kernel(
    const float* __restrict__ Whh, const float* __restrict__ bhh, int ysel)
{
    extern __shared__ char smraw[];
    uint32_t* WBh = (uint32_t*)(smraw + SM_WBH_OFF);   // [j*WROW + kpair]
    uint32_t* WBl = (uint32_t*)(smraw + SM_WBL_OFF);

    const int tid  = threadIdx.x;
    const int bid  = blockIdx.x;
    const int c0   = bid * 8;
    const int warp = tid >> 5;
    const int lane = tid & 31;
    const int mt   = warp & 3;
    const int wgk  = warp >> 2;
    const int l4   = lane >> 2;
    const int tq   = lane & 3;

    const unsigned long long base =
        *(volatile unsigned long long*)&g_flags[bid * 16];

    // ---- pre-split Whh slice into bf16 hi/lo k-pairs (once) ----
    for (int idx = tid; idx < 24 * NKP; idx += GNT) {
        int j  = idx >> 9;
        int kp = idx & (NKP - 1);
        int jg = j >> 3, jc = j & 7;
        const float* wr = Whh + (size_t)(jg * HID + c0 + jc) * HID;
        float w0 = wr[2 * kp], w1 = wr[2 * kp + 1];
        uint16_t h0 = bfbits(w0), h1 = bfbits(w1);
        WBh[j * WROW + kp] = ((uint32_t)h1 << 16) | h0;
        uint16_t l0 = bfbits(w0 - bf2f(h0)), l1 = bfbits(w1 - bf2f(h1));
        WBl[j * WROW + kp] = ((uint32_t)l1 << 16) | l0;
    }

    const int cA = c0 + 2 * tq;
    const int bA = mt * 16 + l4;
    float bh[3][2];
#pragma unroll
    for (int gte = 0; gte < 3; gte++) {
        bh[gte][0] = bhh[gte * HID + cA];
        bh[gte][1] = bhh[gte * HID + cA + 1];
    }

    float hp[4] = {0.f, 0.f, 0.f, 0.f};

    uint32_t* WST = (uint32_t*)(smraw + SM_ST_OFF) + warp * NSTG * STG_U32;
    const uint32_t s_wst = (uint32_t)__cvta_generic_to_shared(WST);

    __syncthreads();

    for (int t = 0; t < SEQ; t++) {
        float xv[3][4];
        if (wgk == 0) {
            const size_t rA = ((size_t)bA * SEQ + t) * G3;
            const size_t rB = ((size_t)(bA + 8) * SEQ + t) * G3;
#pragma unroll
            for (int gte = 0; gte < 3; gte++) {
                xv[gte][0] = __ldcg(&g_xg[rA + gte * HID + cA]);
                xv[gte][1] = __ldcg(&g_xg[rA + gte * HID + cA + 1]);
                xv[gte][2] = __ldcg(&g_xg[rB + gte * HID + cA]);
                xv[gte][3] = __ldcg(&g_xg[rB + gte * HID + cA + 1]);
            }
        }

        float acc[3][4];
#pragma unroll
        for (int nt = 0; nt < 3; nt++)
#pragma unroll
            for (int r = 0; r < 4; r++) acc[nt][r] = 0.f;

        if (t > 0) {
            bar_wait_all(base + (unsigned long long)t);

            const uint32_t* hhi = g_h2hi[t & 1];
            const uint32_t* hlo = g_h2lo[t & 1];

            auto stage = [&](int ch) {
                uint32_t dst = s_wst + (uint32_t)(ch % NSTG) * (STG_U32 * 4);
#pragma unroll
                for (int j = 0; j < 4; j++) {
                    int e   = lane + 32 * j;
                    int arr = e >> 6;
                    int b   = (e >> 2) & 15;
                    int s   = e & 3;
                    const uint32_t* src =
                        (arr ? hlo : hhi) +
                        (size_t)(mt * 16 + b) * NKP + ch * 32 + wgk * 16 + s * 4;
                    cp_async16(dst + (uint32_t)((arr * 16 + b) * SROW + s * 4) * 4,
                               src);
                }
                cp_commit();
            };

#pragma unroll
            for (int ch = 0; ch < NSTG - 1; ch++) stage(ch);

#pragma unroll 1
            for (int ch = 0; ch < NCH; ch++) {
                cp_wait<NSTG - 2>();
                __syncwarp();

                if (ch + NSTG - 1 < NCH) stage(ch + NSTG - 1);
                else cp_commit();

                const uint32_t* HA = WST + (ch % NSTG) * STG_U32;
#pragma unroll
                for (int ks = 0; ks < 2; ks++) {
                    const int ko = ks * 8;
                    uint32_t ah0 = HA[l4 * SROW + ko + tq];
                    uint32_t ah1 = HA[(l4 + 8) * SROW + ko + tq];
                    uint32_t ah2 = HA[l4 * SROW + ko + tq + 4];
                    uint32_t ah3 = HA[(l4 + 8) * SROW + ko + tq + 4];
                    uint32_t al0 = HA[(16 + l4) * SROW + ko + tq];
                    uint32_t al1 = HA[(24 + l4) * SROW + ko + tq];
                    uint32_t al2 = HA[(16 + l4) * SROW + ko + tq + 4];
                    uint32_t al3 = HA[(24 + l4) * SROW + ko + tq + 4];
                    const int kb = ch * 32 + wgk * 16 + ks * 8 + tq;
#pragma unroll
                    for (int nt = 0; nt < 3; nt++) {
                        int j = nt * 8 + l4;
                        uint32_t bh0 = WBh[j * WROW + kb];
                        uint32_t bh1 = WBh[j * WROW + kb + 4];
                        uint32_t bl0 = WBl[j * WROW + kb];
                        uint32_t bl1 = WBl[j * WROW + kb + 4];
                        float* c = acc[nt];
                        mma_bf16(c[0], c[1], c[2], c[3], ah0, ah1, ah2, ah3, bh0, bh1);
                        mma_bf16(c[0], c[1], c[2], c[3], ah0, ah1, ah2, ah3, bl0, bl1);
                        mma_bf16(c[0], c[1], c[2], c[3], al0, al1, al2, al3, bh0, bh1);
                    }
                }
            }

            cp_wait<0>();
            __syncthreads();
            float* red = (float*)(smraw + SM_ST_OFF);
            if (wgk == 1) {
                int o = (mt * 32 + lane) * 12;
#pragma unroll
                for (int nt = 0; nt < 3; nt++)
#pragma unroll
                    for (int r = 0; r < 4; r++)
                        red[o + nt * 4 + r] = acc[nt][r];
            }
            __syncthreads();
            if (wgk == 0) {
                int o = (mt * 32 + lane) * 12;
#pragma unroll
                for (int nt = 0; nt < 3; nt++)
#pragma unroll
                    for (int r = 0; r < 4; r++)
                        acc[nt][r] += red[o + nt * 4 + r];
            }
        }

        // ---- gates, in register (wg0 only) ----
        if (wgk == 0) {
            const int slot = (t + 1) & 1;
            const int kp   = 4 * bid + tq;
            float hcell[2][2];
#pragma unroll
            for (int r = 0; r < 4; r++) {
                int i  = r >> 1, jj = r & 1;
                int ar = 2 * i + jj;
                float rg = fsigmoid(xv[0][ar] + acc[0][ar] + bh[0][jj]);
                float zg = fsigmoid(xv[1][ar] + acc[1][ar] + bh[1][jj]);
                float ng = ftanh(xv[2][ar] + rg * (acc[2][ar] + bh[2][jj]));
                float h  = (1.f - zg) * ng + zg * hp[r];
                hp[r] = h;
                hcell[i][jj] = h;
            }
#pragma unroll
            for (int i = 0; i < 2; i++) {
                int b = bA + 8 * i;
                float h0 = hcell[i][0], h1 = hcell[i][1];
                uint16_t u0 = bfbits(h0), u1 = bfbits(h1);
                uint16_t v0 = bfbits(h0 - bf2f(u0)), v1 = bfbits(h1 - bf2f(u1));
                uint32_t hiP = ((uint32_t)u1 << 16) | u0;
                uint32_t loP = ((uint32_t)v1 << 16) | v0;
                g_h2hi[slot][(size_t)b * NKP + kp] = hiP;
                g_h2lo[slot][(size_t)b * NKP + kp] = loP;

                if (ysel) {
                    size_t yo = ((size_t)b * SEQ + t) * NKP + kp;
                    g_y2hi[ysel - 1][yo] = hiP;
                    g_y2lo[ysel - 1][yo] = loP;
                }
                if (t == SEQ - 1) {
                    g_hb[(size_t)b * HID + cA]     = h0;
                    g_hb[(size_t)b * HID + cA + 1] = h1;
                }
            }
        }

        bar_publish(bid, base + (unsigned long long)(t + 1));
    }
}

// ---------------------------------------------------------------------------
// One-time prep: split W_ih12 into packed bf16 hi/lo pair arrays.
// ---------------------------------------------------------------------------
__global__ __launch_bounds__(256) void split_wih_kernel(
    const float* __restrict__ W12)
{
    size_t i = (size_t)blockIdx.x * 256 + threadIdx.x;   // over 2*G3*NKP
    if (i >= (size_t)2 * G3 * NKP) return;
    int    l = (int)(i / ((size_t)G3 * NKP));
    size_t r = i % ((size_t)G3 * NKP);
    size_t n = r >> 9;
    int    kp = (int)(r & (NKP - 1));
    const float* src = W12 + (size_t)l * G3 * HID + n * HID + 2 * kp;
    float w0 = src[0], w1 = src[1];
    uint16_t h0 = bfbits(w0), h1 = bfbits(w1);
    uint16_t l0 = bfbits(w0 - bf2f(h0)), l1 = bfbits(w1 - bf2f(h1));
    g_wih2hi[l][r] = ((uint32_t)h1 << 16) | h0;
    g_wih2lo[l][r] = ((uint32_t)l1 << 16) | l0;
}

// ---------------------------------------------------------------------------
// bf16 3-split MMA GEMM for xg of layers 1,2 (K=1024, packed kpair operands):
//   g_xg[m,n] = sum_k y[m,k]*Wih[n,k] + bias[n]
// Block 128(M) x 64(N), 4 warps (warp tile 64x32), m16n8k16 bf16,
// hh + hl + lh splits, raw u32 fragments (zero in-loop conversions).
// ---------------------------------------------------------------------------
#define YROW   20                       // u32 per smem row (16 + 4 pad)
#define XA_U   (128 * YROW)             // u32 per A array per stage
#define XB_U   (64 * YROW)              // u32 per B array per stage
#define XSTG_U (2 * XA_U + 2 * XB_U)    // 7680 u32 = 30720 B per stage
#define XNC    (NKP / 16)               // 32 chunks (16 kpairs each)

__global__ __launch_bounds__(128, 2) void gemm_xg_bf16_kernel(
    int slot, int wsel, const float* __restrict__ bias)
{
    const uint32_t* Ahi_g = g_y2hi[slot];
    const uint32_t* Alo_g = g_y2lo[slot];
    const uint32_t* Whi_g = g_wih2hi[wsel];
    const uint32_t* Wlo_g = g_wih2lo[wsel];

    extern __shared__ uint32_t xs[];
    const int tid  = threadIdx.x;
    const int warp = tid >> 5;
    const int lane = tid & 31;
    const int g    = lane >> 2;
    const int tq   = lane & 3;

    const int n0 = blockIdx.x * 64;
    const int m0 = blockIdx.y * 128;
    const int wm = (warp & 1) * 64;
    const int wn = (warp >> 1) * 32;

    const uint32_t s_base = (uint32_t)__cvta_generic_to_shared(xs);

    float acc[4][4][4];
#pragma unroll
    for (int mi = 0; mi < 4; mi++)
#pragma unroll
        for (int ni = 0; ni < 4; ni++)
#pragma unroll
            for (int r = 0; r < 4; r++) acc[mi][ni][r] = 0.f;

    auto load_stage = [&](int ch, int buf) {
        const int kp0 = ch * 16;
        uint32_t dst = s_base + (uint32_t)buf * XSTG_U * 4;
        // A: 128 rows x 4 segs x 2 arrays = 1024 segs -> 8/thread
#pragma unroll
        for (int j = 0; j < 8; j++) {
            int o = tid + j * 128;
            int arr = o >> 9, oo = o & 511;
            int row = oo >> 2, s = oo & 3;
            const uint32_t* src = (arr ? Alo_g : Ahi_g) +
                                  (size_t)(m0 + row) * NKP + kp0 + s * 4;
            cp_async16(dst + (uint32_t)(arr * XA_U + row * YROW + s * 4) * 4, src);
        }
        // B: 64 rows x 4 segs x 2 arrays = 512 segs -> 4/thread
#pragma unroll
        for (int j = 0; j < 4; j++) {
            int o = tid + j * 128;
            int arr = o >> 8, oo = o & 255;
            int row = oo >> 2, s = oo & 3;
            const uint32_t* src = (arr ? Wlo_g : Whi_g) +
                                  (size_t)(n0 + row) * NKP + kp0 + s * 4;
            cp_async16(dst + (uint32_t)(2 * XA_U + arr * XB_U + row * YROW + s * 4) * 4,
                       src);
        }
        cp_commit();
    };

    load_stage(0, 0);
    load_stage(1, 1);

    for (int ch = 0; ch < XNC; ch++) {
        cp_wait<1>();
        __syncthreads();
        const uint32_t* Ah = xs + (ch & 1) * XSTG_U;
        const uint32_t* Al = Ah + XA_U;
        const uint32_t* Bh = Ah + 2 * XA_U;
        const uint32_t* Bl = Bh + XB_U;

#pragma unroll
        for (int ks = 0; ks < 2; ks++) {
            const int ko = ks * 8;
            uint32_t ahi[4][4], alo[4][4];
#pragma unroll
            for (int mi = 0; mi < 4; mi++) {
                int rb = wm + mi * 16 + g;
                ahi[mi][0] = Ah[rb * YROW + ko + tq];
                ahi[mi][1] = Ah[(rb + 8) * YROW + ko + tq];
                ahi[mi][2] = Ah[rb * YROW + ko + tq + 4];
                ahi[mi][3] = Ah[(rb + 8) * YROW + ko + tq + 4];
                alo[mi][0] = Al[rb * YROW + ko + tq];
                alo[mi][1] = Al[(rb + 8) * YROW + ko + tq];
                alo[mi][2] = Al[rb * YROW + ko + tq + 4];
                alo[mi][3] = Al[(rb + 8) * YROW + ko + tq + 4];
            }
            uint32_t bhi[4][2], blo[4][2];
#pragma unroll
            for (int ni = 0; ni < 4; ni++) {
                int nb = wn + ni * 8 + g;
                bhi[ni][0] = Bh[nb * YROW + ko + tq];
                bhi[ni][1] = Bh[nb * YROW + ko + tq + 4];
                blo[ni][0] = Bl[nb * YROW + ko + tq];
                blo[ni][1] = Bl[nb * YROW + ko + tq + 4];
            }
#pragma unroll
            for (int mi = 0; mi < 4; mi++)
#pragma unroll
                for (int ni = 0; ni < 4; ni++) {
                    float* c = acc[mi][ni];
                    mma_bf16(c[0], c[1], c[2], c[3],
                             ahi[mi][0], ahi[mi][1], ahi[mi][2], ahi[mi][3],
                             bhi[ni][0], bhi[ni][1]);
                    mma_bf16(c[0], c[1], c[2], c[3],
                             ahi[mi][0], ahi[mi][1], ahi[mi][2], ahi[mi][3],
                             blo[ni][0], blo[ni][1]);
                    mma_bf16(c[0], c[1], c[2], c[3],
                             alo[mi][0], alo[mi][1], alo[mi][2], alo[mi][3],
                             bhi[ni][0], bhi[ni][1]);
                }
        }

        __syncthreads();
        if (ch + 2 < XNC) load_stage(ch + 2, ch & 1);
        cp_commit();
    }

#pragma unroll
    for (int mi = 0; mi < 4; mi++) {
        int r0 = m0 + wm + mi * 16 + g;
#pragma unroll
        for (int ni = 0; ni < 4; ni++) {
            int cb = n0 + wn + ni * 8 + 2 * tq;
            float2 bia = *(const float2*)&bias[cb];
            float* c = acc[mi][ni];
            *(float2*)&g_xg[(size_t)r0 * G3 + cb] =
                make_float2(c[0] + bia.x, c[1] + bia.y);
            *(float2*)&g_xg[(size_t)(r0 + 8) * G3 + cb] =
                make_float2(c[2] + bia.x, c[3] + bia.y);
        }
    }
}

// ---------------------------------------------------------------------------
// fp32 SGEMM for layer-0 xg (K = 118). (unchanged, passing)
// ---------------------------------------------------------------------------
__global__ __launch_bounds__(256) void gemm_xg_kernel(
    const float* __restrict__ x_in, int K,
    const float* __restrict__ W, const float* __restrict__ bias)
{
    const float* A = x_in;

    __shared__ float As[8][128];
    __shared__ float Bs[8][128];

    const int n0 = blockIdx.x * 128;
    const int m0 = blockIdx.y * 128;
    const int tid = threadIdx.x;
    const int tx = tid & 15;
    const int ty = tid >> 4;

    float acc[8][8];
#pragma unroll
    for (int i = 0; i < 8; i++)
#pragma unroll
        for (int j = 0; j < 8; j++) acc[i][j] = 0.f;

    const int nkt = (K + 7) >> 3;
    for (int kt = 0; kt < nkt; kt++) {
        const int k0 = kt << 3;
#pragma unroll
        for (int i = 0; i < 4; i++) {
            int ii = tid + i * 256;
            int m = ii >> 3, k = ii & 7;
            As[k][m] = (k0 + k < K) ? A[(size_t)(m0 + m) * K + (k0 + k)] : 0.f;
        }
#pragma unroll
        for (int i = 0; i < 4; i++) {
            int ii = tid + i * 256;
            int n = ii >> 3, k = ii & 7;
            Bs[k][n] = (k0 + k < K) ? W[(size_t)(n0 + n) * K + (k0 + k)] : 0.f;
        }
        __syncthreads();
#pragma unroll
        for (int k = 0; k < 8; k++) {
            float a[8], b[8];
#pragma unroll
            for (int i = 0; i < 8; i++) a[i] = As[k][ty * 8 + i];
#pragma unroll
            for (int j = 0; j < 8; j++) b[j] = Bs[k][tx * 8 + j];
#pragma unroll
            for (int i = 0; i < 8; i++)
#pragma unroll
                for (int j = 0; j < 8; j++)
                    acc[i][j] = fmaf(a[i], b[j], acc[i][j]);
        }
        __syncthreads();
    }

#pragma unroll
    for (int i = 0; i < 8; i++) {
        size_t row = (size_t)(m0 + ty * 8 + i) * G3;
#pragma unroll
        for (int j = 0; j < 8; j++) {
            int n = n0 + tx * 8 + j;
            g_xg[row + n] = acc[i][j] + bias[n];
        }
    }
}

// ---------------------------------------------------------------------------
// Final linear: out[b] = dot(h_last[b,:], W_lin) + b_lin
// ---------------------------------------------------------------------------
__global__ __launch_bounds__(256) void final_kernel(
    const float* __restrict__ Wlin, const float* __restrict__ blin,
    float* __restrict__ out)
{
    const int b = blockIdx.x;
    const float* h = g_hb + b * HID;
    float s = 0.f;
    for (int k = threadIdx.x; k < HID; k += 256) s += h[k] * Wlin[k];
#pragma unroll
    for (int o = 16; o > 0; o >>= 1) s += __shfl_down_sync(0xffffffffu, s, o);
    __shared__ float red[8];
    if ((threadIdx.x & 31) == 0) red[threadIdx.x >> 5] = s;
    __syncthreads();
    if (threadIdx.x < 8) {
        s = red[threadIdx.x];
#pragma unroll
        for (int o = 4; o > 0; o >>= 1) s += __shfl_down_sync(0xffu, s, o);
        if (threadIdx.x == 0) out[b] = s + blin[0];
    }
}

// ---------------------------------------------------------------------------
extern "C" void kernel_launch(void* const* d_in, const int* in_sizes, int n_in,
                              void* d_out, int out_size)
{
    const float* x      = (const float*)d_in[0];
    const float* W_ih0  = (const float*)d_in[1];
    const float* W_ih12 = (const float*)d_in[2];
    const float* W_hh   = (const float*)d_in[3];
    const float* b_ih   = (const float*)d_in[4];
    const float* b_hh   = (const float*)d_in[5];
    const float* W_lin  = (const float*)d_in[6];
    const float* b_lin  = (const float*)d_in[7];
    float* out = (float*)d_out;

    cudaFuncSetAttribute(gru_layer_kernel,
                         cudaFuncAttributeMaxDynamicSharedMemorySize, GSM_BYTES);
    const int smem_xgb = 2 * XSTG_U * 4;   // 61440 B
    cudaFuncSetAttribute(gemm_xg_bf16_kernel,
                         cudaFuncAttributeMaxDynamicSharedMemorySize, smem_xgb);

    // one-time W_ih12 split (graph-capturable, deterministic)
    {
        size_t tot = (size_t)2 * G3 * NKP;
        split_wih_kernel<<<(unsigned)((tot + 255) / 256), 256>>>(W_ih12);
    }

    for (int l = 0; l < 3; l++) {
        const int    ysel  = (l == 0) ? 1 : (l == 1 ? 2 : 0);
        const float* Whh_l = W_hh + (size_t)l * G3 * HID;
        const float* bih_l = b_ih + (size_t)l * G3;
        const float* bhh_l = b_hh + (size_t)l * G3;

        if (l == 0) {
            dim3 ggrid(G3 / 128, BT / 128);
            gemm_xg_kernel<<<ggrid, 256>>>(x, DIN0, W_ih0, bih_l);
        } else {
            dim3 ggrid(G3 / 64, BT / 128);
            gemm_xg_bf16_kernel<<<ggrid, 128, smem_xgb>>>(l - 1, l - 1, bih_l);
        }

        gru_layer_kernel<<<NBLK, GNT, GSM_BYTES>>>(Whh_l, bhh_l, ysel);
    }

    final_kernel<<<BATCH, 256>>>(W_lin, b_lin, out);
}

// round 16
// speedup vs baseline: 2.8220x; 1.2210x over previous
#include <cuda_runtime.h>
#include <cuda_bf16.h>
#include <cuda_fp16.h>
#include <cstdint>

#define HID   1024
#define BATCH 64
#define SEQ   512
#define G3    3072
#define BT    (BATCH * SEQ)
#define DIN0  118
#define NKP   512          // packed k-pairs per row (HID/2)

#define NBLK  128          // persistent blocks (all co-resident; <= 148 SMs)
#define GNT   256          // 8 warps: mt = warp&3 (m-tile), wgk = warp>>2 (k-half)
#define NCH   16           // h chunks per step (64 k-rows = 32 u32 pairs each)
#define NSTG  6            // per-warp ring stages
#define SROW  20           // u32 per stage row (16 data + 4 pad; conflict-free)
#define STG_U32 (16 * SROW)            // 320 u32 per stage (16 fp16-pair rows)
#define WROW  516                      // u32 per smem W row (512 + 4 pad)
#define SM_WBH_OFF 0
#define SM_WBL_OFF (24 * WROW * 4)                     // 49536
#define SM_ST_OFF  (2 * 24 * WROW * 4)                 // 99072
#define GSM_BYTES  (SM_ST_OFF + 8 * NSTG * STG_U32 * 4)  // 99072+61440 = 160512

// ---------------- scratch (device globals; no allocation allowed) ----------
__device__ float    g_xg[(size_t)BT * G3];    // input projections for current layer
__device__ uint32_t g_y2hi[2][(size_t)BT * NKP];  // layer outputs, packed bf16-hi pairs
__device__ uint32_t g_y2lo[2][(size_t)BT * NKP];  // packed bf16 residual pairs
__device__ uint32_t g_wih2hi[2][(size_t)G3 * NKP]; // W_ih12 packed bf16-hi
__device__ uint32_t g_wih2lo[2][(size_t)G3 * NKP]; // W_ih12 packed bf16-lo
__device__ uint32_t g_hf16[2][BATCH * NKP];   // h fp16 pairs [b][kpair], ping-pong
__device__ float    g_hb[BATCH * HID];        // final hidden, batch-major
__device__ unsigned long long g_flags[NBLK * 16];  // per-block step counters

__device__ __forceinline__ float fsigmoid(float x) {
    return 1.f / (1.f + __expf(-x));
}
__device__ __forceinline__ float ftanh(float x) {
    return 2.f / (1.f + __expf(-2.f * x)) - 1.f;
}
__device__ __forceinline__ uint16_t bfbits(float x) {
    __nv_bfloat16 b = __float2bfloat16(x);
    return *(uint16_t*)&b;
}
__device__ __forceinline__ float bf2f(uint16_t u) {
    __nv_bfloat16 b = *(__nv_bfloat16*)&u;
    return __bfloat162float(b);
}
__device__ __forceinline__ uint16_t hfbits(float x) {
    __half h = __float2half_rn(x);
    return *(uint16_t*)&h;
}
__device__ __forceinline__ float hf2f(uint16_t u) {
    __half h = *(__half*)&u;
    return __half2float(h);
}

// ---------------------------------------------------------------------------
// cp.async / mma helpers
// ---------------------------------------------------------------------------
__device__ __forceinline__ void cp_async16(uint32_t smem_dst, const void* gptr) {
    asm volatile("cp.async.cg.shared.global [%0], [%1], 16;\n"
                 :: "r"(smem_dst), "l"(gptr));
}
__device__ __forceinline__ void cp_commit() {
    asm volatile("cp.async.commit_group;\n");
}
template <int N>
__device__ __forceinline__ void cp_wait() {
    asm volatile("cp.async.wait_group %0;\n" :: "n"(N));
}
__device__ __forceinline__ void mma_bf16(
    float& c0, float& c1, float& c2, float& c3,
    uint32_t a0, uint32_t a1, uint32_t a2, uint32_t a3,
    uint32_t b0, uint32_t b1)
{
    asm volatile(
        "mma.sync.aligned.m16n8k16.row.col.f32.bf16.bf16.f32 "
        "{%0,%1,%2,%3}, {%4,%5,%6,%7}, {%8,%9}, {%0,%1,%2,%3};"
        : "+f"(c0), "+f"(c1), "+f"(c2), "+f"(c3)
        : "r"(a0), "r"(a1), "r"(a2), "r"(a3), "r"(b0), "r"(b1));
}
__device__ __forceinline__ void mma_f16(
    float& c0, float& c1, float& c2, float& c3,
    uint32_t a0, uint32_t a1, uint32_t a2, uint32_t a3,
    uint32_t b0, uint32_t b1)
{
    asm volatile(
        "mma.sync.aligned.m16n8k16.row.col.f32.f16.f16.f32 "
        "{%0,%1,%2,%3}, {%4,%5,%6,%7}, {%8,%9}, {%0,%1,%2,%3};"
        : "+f"(c0), "+f"(c1), "+f"(c2), "+f"(c3)
        : "r"(a0), "r"(a1), "r"(a2), "r"(a3), "r"(b0), "r"(b1));
}

// ---------------------------------------------------------------------------
// Distributed one-hop barrier (proven R12-R15). ONE poll per step.
// ---------------------------------------------------------------------------
__device__ __forceinline__ void bar_publish(int bid, unsigned long long val) {
    __threadfence();
    __syncthreads();
    if (threadIdx.x == 0)
        *(volatile unsigned long long*)&g_flags[bid * 16] = val;
}
__device__ __forceinline__ void bar_wait_all(unsigned long long tgt) {
    const int tid = threadIdx.x;
    if (tid < NBLK) {
        while (*(volatile unsigned long long*)&g_flags[tid * 16] < tgt)
            __nanosleep(32);
        __threadfence();
    }
    __syncthreads();
}

// ---------------------------------------------------------------------------
// Persistent per-layer GRU kernel — fp16 2-split recurrence (hh + hl):
// h carried fp32 IN REGISTER; published as single fp16 pair stream (halves
// the all-to-all L2 broadcast). W pre-split into fp16 hi + fp16 lo in smem.
// Warp-private 6-deep staging rings; one distributed barrier per step.
// ---------------------------------------------------------------------------
__global__ __launch_bounds__(GNT, 1) void gru_layer_kernel(
    const float* __restrict__ Whh, const float* __restrict__ bhh, int ysel)
{
    extern __shared__ char smraw[];
    uint32_t* WBh = (uint32_t*)(smraw + SM_WBH_OFF);   // fp16-hi pairs [j*WROW+kp]
    uint32_t* WBl = (uint32_t*)(smraw + SM_WBL_OFF);   // fp16-lo pairs

    const int tid  = threadIdx.x;
    const int bid  = blockIdx.x;
    const int c0   = bid * 8;
    const int warp = tid >> 5;
    const int lane = tid & 31;
    const int mt   = warp & 3;
    const int wgk  = warp >> 2;
    const int l4   = lane >> 2;
    const int tq   = lane & 3;

    const unsigned long long base =
        *(volatile unsigned long long*)&g_flags[bid * 16];

    // ---- pre-split Whh slice into fp16 hi/lo k-pairs (once) ----
    for (int idx = tid; idx < 24 * NKP; idx += GNT) {
        int j  = idx >> 9;
        int kp = idx & (NKP - 1);
        int jg = j >> 3, jc = j & 7;
        const float* wr = Whh + (size_t)(jg * HID + c0 + jc) * HID;
        float w0 = wr[2 * kp], w1 = wr[2 * kp + 1];
        uint16_t h0 = hfbits(w0), h1 = hfbits(w1);
        WBh[j * WROW + kp] = ((uint32_t)h1 << 16) | h0;
        uint16_t l0 = hfbits(w0 - hf2f(h0)), l1 = hfbits(w1 - hf2f(h1));
        WBl[j * WROW + kp] = ((uint32_t)l1 << 16) | l0;
    }

    const int cA = c0 + 2 * tq;
    const int bA = mt * 16 + l4;
    float bh[3][2];
#pragma unroll
    for (int gte = 0; gte < 3; gte++) {
        bh[gte][0] = bhh[gte * HID + cA];
        bh[gte][1] = bhh[gte * HID + cA + 1];
    }

    float hp[4] = {0.f, 0.f, 0.f, 0.f};   // fp32 recurrence state, in register

    uint32_t* WST = (uint32_t*)(smraw + SM_ST_OFF) + warp * NSTG * STG_U32;
    const uint32_t s_wst = (uint32_t)__cvta_generic_to_shared(WST);

    __syncthreads();

    for (int t = 0; t < SEQ; t++) {
        float xv[3][4];
        if (wgk == 0) {
            const size_t rA = ((size_t)bA * SEQ + t) * G3;
            const size_t rB = ((size_t)(bA + 8) * SEQ + t) * G3;
#pragma unroll
            for (int gte = 0; gte < 3; gte++) {
                xv[gte][0] = __ldcg(&g_xg[rA + gte * HID + cA]);
                xv[gte][1] = __ldcg(&g_xg[rA + gte * HID + cA + 1]);
                xv[gte][2] = __ldcg(&g_xg[rB + gte * HID + cA]);
                xv[gte][3] = __ldcg(&g_xg[rB + gte * HID + cA + 1]);
            }
        }

        float acc[3][4];
#pragma unroll
        for (int nt = 0; nt < 3; nt++)
#pragma unroll
            for (int r = 0; r < 4; r++) acc[nt][r] = 0.f;

        if (t > 0) {
            bar_wait_all(base + (unsigned long long)t);

            const uint32_t* hsrc = g_hf16[t & 1];

            // per-warp stage: 16 batches x 16 u32 fp16-pairs = 64 segs, 2/lane
            auto stage = [&](int ch) {
                uint32_t dst = s_wst + (uint32_t)(ch % NSTG) * (STG_U32 * 4);
#pragma unroll
                for (int j = 0; j < 2; j++) {
                    int e = lane + 32 * j;          // 0..63
                    int b = e >> 2, s = e & 3;
                    const uint32_t* src = hsrc +
                        (size_t)(mt * 16 + b) * NKP + ch * 32 + wgk * 16 + s * 4;
                    cp_async16(dst + (uint32_t)(b * SROW + s * 4) * 4, src);
                }
                cp_commit();
            };

#pragma unroll
            for (int ch = 0; ch < NSTG - 1; ch++) stage(ch);

#pragma unroll 1
            for (int ch = 0; ch < NCH; ch++) {
                cp_wait<NSTG - 2>();
                __syncwarp();

                if (ch + NSTG - 1 < NCH) stage(ch + NSTG - 1);
                else cp_commit();

                const uint32_t* HA = WST + (ch % NSTG) * STG_U32;
#pragma unroll
                for (int ks = 0; ks < 2; ks++) {
                    const int ko = ks * 8;
                    uint32_t ah0 = HA[l4 * SROW + ko + tq];
                    uint32_t ah1 = HA[(l4 + 8) * SROW + ko + tq];
                    uint32_t ah2 = HA[l4 * SROW + ko + tq + 4];
                    uint32_t ah3 = HA[(l4 + 8) * SROW + ko + tq + 4];
                    const int kb = ch * 32 + wgk * 16 + ks * 8 + tq;
#pragma unroll
                    for (int nt = 0; nt < 3; nt++) {
                        int j = nt * 8 + l4;
                        uint32_t bh0 = WBh[j * WROW + kb];
                        uint32_t bh1 = WBh[j * WROW + kb + 4];
                        uint32_t bl0 = WBl[j * WROW + kb];
                        uint32_t bl1 = WBl[j * WROW + kb + 4];
                        float* c = acc[nt];
                        mma_f16(c[0], c[1], c[2], c[3], ah0, ah1, ah2, ah3, bh0, bh1);
                        mma_f16(c[0], c[1], c[2], c[3], ah0, ah1, ah2, ah3, bl0, bl1);
                    }
                }
            }

            cp_wait<0>();
            __syncthreads();
            float* red = (float*)(smraw + SM_ST_OFF);
            if (wgk == 1) {
                int o = (mt * 32 + lane) * 12;
#pragma unroll
                for (int nt = 0; nt < 3; nt++)
#pragma unroll
                    for (int r = 0; r < 4; r++)
                        red[o + nt * 4 + r] = acc[nt][r];
            }
            __syncthreads();
            if (wgk == 0) {
                int o = (mt * 32 + lane) * 12;
#pragma unroll
                for (int nt = 0; nt < 3; nt++)
#pragma unroll
                    for (int r = 0; r < 4; r++)
                        acc[nt][r] += red[o + nt * 4 + r];
            }
        }

        // ---- gates, fp32 in register (wg0 only) ----
        if (wgk == 0) {
            const int slot = (t + 1) & 1;
            const int kp   = 4 * bid + tq;
            float hcell[2][2];
#pragma unroll
            for (int r = 0; r < 4; r++) {
                int i  = r >> 1, jj = r & 1;
                int ar = 2 * i + jj;
                float rg = fsigmoid(xv[0][ar] + acc[0][ar] + bh[0][jj]);
                float zg = fsigmoid(xv[1][ar] + acc[1][ar] + bh[1][jj]);
                float ng = ftanh(xv[2][ar] + rg * (acc[2][ar] + bh[2][jj]));
                float h  = (1.f - zg) * ng + zg * hp[r];
                hp[r] = h;
                hcell[i][jj] = h;
            }
#pragma unroll
            for (int i = 0; i < 2; i++) {
                int b = bA + 8 * i;
                float h0 = hcell[i][0], h1 = hcell[i][1];
                // fp16 pair for the recurrent broadcast (single stream)
                g_hf16[slot][(size_t)b * NKP + kp] =
                    ((uint32_t)hfbits(h1) << 16) | hfbits(h0);

                if (ysel) {
                    // bf16 hi/lo pairs for the (full-precision) xg path
                    uint16_t u0 = bfbits(h0), u1 = bfbits(h1);
                    uint16_t v0 = bfbits(h0 - bf2f(u0)), v1 = bfbits(h1 - bf2f(u1));
                    size_t yo = ((size_t)b * SEQ + t) * NKP + kp;
                    g_y2hi[ysel - 1][yo] = ((uint32_t)u1 << 16) | u0;
                    g_y2lo[ysel - 1][yo] = ((uint32_t)v1 << 16) | v0;
                }
                if (t == SEQ - 1) {
                    g_hb[(size_t)b * HID + cA]     = h0;
                    g_hb[(size_t)b * HID + cA + 1] = h1;
                }
            }
        }

        bar_publish(bid, base + (unsigned long long)(t + 1));
    }
}

// ---------------------------------------------------------------------------
// One-time prep: split W_ih12 into packed bf16 hi/lo pair arrays.
// ---------------------------------------------------------------------------
__global__ __launch_bounds__(256) void split_wih_kernel(
    const float* __restrict__ W12)
{
    size_t i = (size_t)blockIdx.x * 256 + threadIdx.x;
    if (i >= (size_t)2 * G3 * NKP) return;
    int    l = (int)(i / ((size_t)G3 * NKP));
    size_t r = i % ((size_t)G3 * NKP);
    size_t n = r >> 9;
    int    kp = (int)(r & (NKP - 1));
    const float* src = W12 + (size_t)l * G3 * HID + n * HID + 2 * kp;
    float w0 = src[0], w1 = src[1];
    uint16_t h0 = bfbits(w0), h1 = bfbits(w1);
    uint16_t l0 = bfbits(w0 - bf2f(h0)), l1 = bfbits(w1 - bf2f(h1));
    g_wih2hi[l][r] = ((uint32_t)h1 << 16) | h0;
    g_wih2lo[l][r] = ((uint32_t)l1 << 16) | l0;
}

// ---------------------------------------------------------------------------
// bf16 3-split MMA GEMM for xg of layers 1,2. (unchanged, passing)
// ---------------------------------------------------------------------------
#define YROW   20
#define XA_U   (128 * YROW)
#define XB_U   (64 * YROW)
#define XSTG_U (2 * XA_U + 2 * XB_U)
#define XNC    (NKP / 16)

__global__ __launch_bounds__(128, 2) void gemm_xg_bf16_kernel(
    int slot, int wsel, const float* __restrict__ bias)
{
    const uint32_t* Ahi_g = g_y2hi[slot];
    const uint32_t* Alo_g = g_y2lo[slot];
    const uint32_t* Whi_g = g_wih2hi[wsel];
    const uint32_t* Wlo_g = g_wih2lo[wsel];

    extern __shared__ uint32_t xs[];
    const int tid  = threadIdx.x;
    const int warp = tid >> 5;
    const int lane = tid & 31;
    const int g    = lane >> 2;
    const int tq   = lane & 3;

    const int n0 = blockIdx.x * 64;
    const int m0 = blockIdx.y * 128;
    const int wm = (warp & 1) * 64;
    const int wn = (warp >> 1) * 32;

    const uint32_t s_base = (uint32_t)__cvta_generic_to_shared(xs);

    float acc[4][4][4];
#pragma unroll
    for (int mi = 0; mi < 4; mi++)
#pragma unroll
        for (int ni = 0; ni < 4; ni++)
#pragma unroll
            for (int r = 0; r < 4; r++) acc[mi][ni][r] = 0.f;

    auto load_stage = [&](int ch, int buf) {
        const int kp0 = ch * 16;
        uint32_t dst = s_base + (uint32_t)buf * XSTG_U * 4;
#pragma unroll
        for (int j = 0; j < 8; j++) {
            int o = tid + j * 128;
            int arr = o >> 9, oo = o & 511;
            int row = oo >> 2, s = oo & 3;
            const uint32_t* src = (arr ? Alo_g : Ahi_g) +
                                  (size_t)(m0 + row) * NKP + kp0 + s * 4;
            cp_async16(dst + (uint32_t)(arr * XA_U + row * YROW + s * 4) * 4, src);
        }
#pragma unroll
        for (int j = 0; j < 4; j++) {
            int o = tid + j * 128;
            int arr = o >> 8, oo = o & 255;
            int row = oo >> 2, s = oo & 3;
            const uint32_t* src = (arr ? Wlo_g : Whi_g) +
                                  (size_t)(n0 + row) * NKP + kp0 + s * 4;
            cp_async16(dst + (uint32_t)(2 * XA_U + arr * XB_U + row * YROW + s * 4) * 4,
                       src);
        }
        cp_commit();
    };

    load_stage(0, 0);
    load_stage(1, 1);

    for (int ch = 0; ch < XNC; ch++) {
        cp_wait<1>();
        __syncthreads();
        const uint32_t* Ah = xs + (ch & 1) * XSTG_U;
        const uint32_t* Al = Ah + XA_U;
        const uint32_t* Bh = Ah + 2 * XA_U;
        const uint32_t* Bl = Bh + XB_U;

#pragma unroll
        for (int ks = 0; ks < 2; ks++) {
            const int ko = ks * 8;
            uint32_t ahi[4][4], alo[4][4];
#pragma unroll
            for (int mi = 0; mi < 4; mi++) {
                int rb = wm + mi * 16 + g;
                ahi[mi][0] = Ah[rb * YROW + ko + tq];
                ahi[mi][1] = Ah[(rb + 8) * YROW + ko + tq];
                ahi[mi][2] = Ah[rb * YROW + ko + tq + 4];
                ahi[mi][3] = Ah[(rb + 8) * YROW + ko + tq + 4];
                alo[mi][0] = Al[rb * YROW + ko + tq];
                alo[mi][1] = Al[(rb + 8) * YROW + ko + tq];
                alo[mi][2] = Al[rb * YROW + ko + tq + 4];
                alo[mi][3] = Al[(rb + 8) * YROW + ko + tq + 4];
            }
            uint32_t bhi[4][2], blo[4][2];
#pragma unroll
            for (int ni = 0; ni < 4; ni++) {
                int nb = wn + ni * 8 + g;
                bhi[ni][0] = Bh[nb * YROW + ko + tq];
                bhi[ni][1] = Bh[nb * YROW + ko + tq + 4];
                blo[ni][0] = Bl[nb * YROW + ko + tq];
                blo[ni][1] = Bl[nb * YROW + ko + tq + 4];
            }
#pragma unroll
            for (int mi = 0; mi < 4; mi++)
#pragma unroll
                for (int ni = 0; ni < 4; ni++) {
                    float* c = acc[mi][ni];
                    mma_bf16(c[0], c[1], c[2], c[3],
                             ahi[mi][0], ahi[mi][1], ahi[mi][2], ahi[mi][3],
                             bhi[ni][0], bhi[ni][1]);
                    mma_bf16(c[0], c[1], c[2], c[3],
                             ahi[mi][0], ahi[mi][1], ahi[mi][2], ahi[mi][3],
                             blo[ni][0], blo[ni][1]);
                    mma_bf16(c[0], c[1], c[2], c[3],
                             alo[mi][0], alo[mi][1], alo[mi][2], alo[mi][3],
                             bhi[ni][0], bhi[ni][1]);
                }
        }

        __syncthreads();
        if (ch + 2 < XNC) load_stage(ch + 2, ch & 1);
        cp_commit();
    }

#pragma unroll
    for (int mi = 0; mi < 4; mi++) {
        int r0 = m0 + wm + mi * 16 + g;
#pragma unroll
        for (int ni = 0; ni < 4; ni++) {
            int cb = n0 + wn + ni * 8 + 2 * tq;
            float2 bia = *(const float2*)&bias[cb];
            float* c = acc[mi][ni];
            *(float2*)&g_xg[(size_t)r0 * G3 + cb] =
                make_float2(c[0] + bia.x, c[1] + bia.y);
            *(float2*)&g_xg[(size_t)(r0 + 8) * G3 + cb] =
                make_float2(c[2] + bia.x, c[3] + bia.y);
        }
    }
}

// ---------------------------------------------------------------------------
// fp32 SGEMM for layer-0 xg (K = 118). (unchanged, passing)
// ---------------------------------------------------------------------------
__global__ __launch_bounds__(256) void gemm_xg_kernel(
    const float* __restrict__ x_in, int K,
    const float* __restrict__ W, const float* __restrict__ bias)
{
    const float* A = x_in;

    __shared__ float As[8][128];
    __shared__ float Bs[8][128];

    const int n0 = blockIdx.x * 128;
    const int m0 = blockIdx.y * 128;
    const int tid = threadIdx.x;
    const int tx = tid & 15;
    const int ty = tid >> 4;

    float acc[8][8];
#pragma unroll
    for (int i = 0; i < 8; i++)
#pragma unroll
        for (int j = 0; j < 8; j++) acc[i][j] = 0.f;

    const int nkt = (K + 7) >> 3;
    for (int kt = 0; kt < nkt; kt++) {
        const int k0 = kt << 3;
#pragma unroll
        for (int i = 0; i < 4; i++) {
            int ii = tid + i * 256;
            int m = ii >> 3, k = ii & 7;
            As[k][m] = (k0 + k < K) ? A[(size_t)(m0 + m) * K + (k0 + k)] : 0.f;
        }
#pragma unroll
        for (int i = 0; i < 4; i++) {
            int ii = tid + i * 256;
            int n = ii >> 3, k = ii & 7;
            Bs[k][n] = (k0 + k < K) ? W[(size_t)(n0 + n) * K + (k0 + k)] : 0.f;
        }
        __syncthreads();
#pragma unroll
        for (int k = 0; k < 8; k++) {
            float a[8], b[8];
#pragma unroll
            for (int i = 0; i < 8; i++) a[i] = As[k][ty * 8 + i];
#pragma unroll
            for (int j = 0; j < 8; j++) b[j] = Bs[k][tx * 8 + j];
#pragma unroll
            for (int i = 0; i < 8; i++)
#pragma unroll
                for (int j = 0; j < 8; j++)
                    acc[i][j] = fmaf(a[i], b[j], acc[i][j]);
        }
        __syncthreads();
    }

#pragma unroll
    for (int i = 0; i < 8; i++) {
        size_t row = (size_t)(m0 + ty * 8 + i) * G3;
#pragma unroll
        for (int j = 0; j < 8; j++) {
            int n = n0 + tx * 8 + j;
            g_xg[row + n] = acc[i][j] + bias[n];
        }
    }
}

// ---------------------------------------------------------------------------
// Final linear: out[b] = dot(h_last[b,:], W_lin) + b_lin
// ---------------------------------------------------------------------------
__global__ __launch_bounds__(256) void final_kernel(
    const float* __restrict__ Wlin, const float* __restrict__ blin,
    float* __restrict__ out)
{
    const int b = blockIdx.x;
    const float* h = g_hb + b * HID;
    float s = 0.f;
    for (int k = threadIdx.x; k < HID; k += 256) s += h[k] * Wlin[k];
#pragma unroll
    for (int o = 16; o > 0; o >>= 1) s += __shfl_down_sync(0xffffffffu, s, o);
    __shared__ float red[8];
    if ((threadIdx.x & 31) == 0) red[threadIdx.x >> 5] = s;
    __syncthreads();
    if (threadIdx.x < 8) {
        s = red[threadIdx.x];
#pragma unroll
        for (int o = 4; o > 0; o >>= 1) s += __shfl_down_sync(0xffu, s, o);
        if (threadIdx.x == 0) out[b] = s + blin[0];
    }
}

// ---------------------------------------------------------------------------
extern "C" void kernel_launch(void* const* d_in, const int* in_sizes, int n_in,
                              void* d_out, int out_size)
{
    const float* x      = (const float*)d_in[0];
    const float* W_ih0  = (const float*)d_in[1];
    const float* W_ih12 = (const float*)d_in[2];
    const float* W_hh   = (const float*)d_in[3];
    const float* b_ih   = (const float*)d_in[4];
    const float* b_hh   = (const float*)d_in[5];
    const float* W_lin  = (const float*)d_in[6];
    const float* b_lin  = (const float*)d_in[7];
    float* out = (float*)d_out;

    cudaFuncSetAttribute(gru_layer_kernel,
                         cudaFuncAttributeMaxDynamicSharedMemorySize, GSM_BYTES);
    const int smem_xgb = 2 * XSTG_U * 4;
    cudaFuncSetAttribute(gemm_xg_bf16_kernel,
                         cudaFuncAttributeMaxDynamicSharedMemorySize, smem_xgb);

    {
        size_t tot = (size_t)2 * G3 * NKP;
        split_wih_kernel<<<(unsigned)((tot + 255) / 256), 256>>>(W_ih12);
    }

    for (int l = 0; l < 3; l++) {
        const int    ysel  = (l == 0) ? 1 : (l == 1 ? 2 : 0);
        const float* Whh_l = W_hh + (size_t)l * G3 * HID;
        const float* bih_l = b_ih + (size_t)l * G3;
        const float* bhh_l = b_hh + (size_t)l * G3;

        if (l == 0) {
            dim3 ggrid(G3 / 128, BT / 128);
            gemm_xg_kernel<<<ggrid, 256>>>(x, DIN0, W_ih0, bih_l);
        } else {
            dim3 ggrid(G3 / 64, BT / 128);
            gemm_xg_bf16_kernel<<<ggrid, 128, smem_xgb>>>(l - 1, l - 1, bih_l);
        }

        gru_layer_kernel<<<NBLK, GNT, GSM_BYTES>>>(Whh_l, bhh_l, ysel);
    }

    final_kernel<<<BATCH, 256>>>(W_lin, b_lin, out);
}

// round 17
// speedup vs baseline: 3.0665x; 1.0866x over previous
#include <cuda_runtime.h>
#include <cuda_bf16.h>
#include <cuda_fp16.h>
#include <cstdint>

#define HID   1024
#define BATCH 64
#define SEQ   512
#define G3    3072
#define BT    (BATCH * SEQ)
#define DIN0  118
#define NKP   512          // packed k-pairs per row (HID/2)

#define NBLK  128          // persistent blocks (all co-resident; <= 148 SMs)
#define GNT   256          // 8 warps: mt = warp&3 (m-tile), wgk = warp>>2 (k-half)
#define NCH   16           // h chunks per step (64 k-rows = 32 u32 pairs each)
#define NSTG  6            // per-warp ring stages
#define SROW  20           // u32 per stage row (16 data + 4 pad; conflict-free)
#define STG_U32 (16 * SROW)            // 320 u32 per stage (16 fp16-pair rows)
#define WROW  516                      // u32 per smem W row (512 + 4 pad)
#define SM_WBH_OFF 0
#define SM_ST_OFF  (24 * WROW * 4)                     // 49536 (single fp16 W)
#define GSM_BYTES  (SM_ST_OFF + 8 * NSTG * STG_U32 * 4)  // 49536+61440 = 110976

// ---------------- scratch (device globals; no allocation allowed) ----------
__device__ float    g_xg[(size_t)BT * G3];    // input projections for current layer
__device__ uint32_t g_y2hi[2][(size_t)BT * NKP];  // layer outputs, packed bf16-hi pairs
__device__ uint32_t g_y2lo[2][(size_t)BT * NKP];  // packed bf16 residual pairs
__device__ uint32_t g_wih2hi[2][(size_t)G3 * NKP]; // W_ih12 packed bf16-hi
__device__ uint32_t g_wih2lo[2][(size_t)G3 * NKP]; // W_ih12 packed bf16-lo
__device__ uint32_t g_hf16[2][BATCH * NKP];   // h fp16 pairs [b][kpair], ping-pong
__device__ float    g_hb[BATCH * HID];        // final hidden, batch-major
__device__ unsigned long long g_flags[NBLK * 16];  // per-block step counters

__device__ __forceinline__ float fsigmoid(float x) {
    return 1.f / (1.f + __expf(-x));
}
__device__ __forceinline__ float ftanh(float x) {
    return 2.f / (1.f + __expf(-2.f * x)) - 1.f;
}
__device__ __forceinline__ uint16_t bfbits(float x) {
    __nv_bfloat16 b = __float2bfloat16(x);
    return *(uint16_t*)&b;
}
__device__ __forceinline__ float bf2f(uint16_t u) {
    __nv_bfloat16 b = *(__nv_bfloat16*)&u;
    return __bfloat162float(b);
}
__device__ __forceinline__ uint16_t hfbits(float x) {
    __half h = __float2half_rn(x);
    return *(uint16_t*)&h;
}

// ---------------------------------------------------------------------------
// cp.async / mma helpers
// ---------------------------------------------------------------------------
__device__ __forceinline__ void cp_async16(uint32_t smem_dst, const void* gptr) {
    asm volatile("cp.async.cg.shared.global [%0], [%1], 16;\n"
                 :: "r"(smem_dst), "l"(gptr));
}
__device__ __forceinline__ void cp_commit() {
    asm volatile("cp.async.commit_group;\n");
}
template <int N>
__device__ __forceinline__ void cp_wait() {
    asm volatile("cp.async.wait_group %0;\n" :: "n"(N));
}
__device__ __forceinline__ void mma_bf16(
    float& c0, float& c1, float& c2, float& c3,
    uint32_t a0, uint32_t a1, uint32_t a2, uint32_t a3,
    uint32_t b0, uint32_t b1)
{
    asm volatile(
        "mma.sync.aligned.m16n8k16.row.col.f32.bf16.bf16.f32 "
        "{%0,%1,%2,%3}, {%4,%5,%6,%7}, {%8,%9}, {%0,%1,%2,%3};"
        : "+f"(c0), "+f"(c1), "+f"(c2), "+f"(c3)
        : "r"(a0), "r"(a1), "r"(a2), "r"(a3), "r"(b0), "r"(b1));
}
__device__ __forceinline__ void mma_f16(
    float& c0, float& c1, float& c2, float& c3,
    uint32_t a0, uint32_t a1, uint32_t a2, uint32_t a3,
    uint32_t b0, uint32_t b1)
{
    asm volatile(
        "mma.sync.aligned.m16n8k16.row.col.f32.f16.f16.f32 "
        "{%0,%1,%2,%3}, {%4,%5,%6,%7}, {%8,%9}, {%0,%1,%2,%3};"
        : "+f"(c0), "+f"(c1), "+f"(c2), "+f"(c3)
        : "r"(a0), "r"(a1), "r"(a2), "r"(a3), "r"(b0), "r"(b1));
}

// ---------------------------------------------------------------------------
// Distributed one-hop barrier (proven R12-R16). ONE poll per step.
// ---------------------------------------------------------------------------
__device__ __forceinline__ void bar_publish(int bid, unsigned long long val) {
    __threadfence();
    __syncthreads();
    if (threadIdx.x == 0)
        *(volatile unsigned long long*)&g_flags[bid * 16] = val;
}
__device__ __forceinline__ void bar_wait_all(unsigned long long tgt) {
    const int tid = threadIdx.x;
    if (tid < NBLK) {
        while (*(volatile unsigned long long*)&g_flags[tid * 16] < tgt)
            __nanosleep(32);
        __threadfence();
    }
    __syncthreads();
}

// ---------------------------------------------------------------------------
// Persistent per-layer GRU kernel — single-fp16 recurrent GEMM:
// h fp32 IN REGISTER across steps; published as one fp16 pair stream.
// W single fp16 in smem (49.5 KB). 96 mma/warp/step. Warp-private 6-deep
// staging rings; one distributed barrier per step.
// ---------------------------------------------------------------------------
__global__ __launch_bounds__(GNT, 1) void gru_layer_kernel(
    const float* __restrict__ Whh, const float* __restrict__ bhh, int ysel)
{
    extern __shared__ char smraw[];
    uint32_t* WBh = (uint32_t*)(smraw + SM_WBH_OFF);   // fp16 pairs [j*WROW+kp]

    const int tid  = threadIdx.x;
    const int bid  = blockIdx.x;
    const int c0   = bid * 8;
    const int warp = tid >> 5;
    const int lane = tid & 31;
    const int mt   = warp & 3;
    const int wgk  = warp >> 2;
    const int l4   = lane >> 2;
    const int tq   = lane & 3;

    const unsigned long long base =
        *(volatile unsigned long long*)&g_flags[bid * 16];

    // ---- pre-convert Whh slice to fp16 k-pairs (once) ----
    for (int idx = tid; idx < 24 * NKP; idx += GNT) {
        int j  = idx >> 9;
        int kp = idx & (NKP - 1);
        int jg = j >> 3, jc = j & 7;
        const float* wr = Whh + (size_t)(jg * HID + c0 + jc) * HID;
        WBh[j * WROW + kp] =
            ((uint32_t)hfbits(wr[2 * kp + 1]) << 16) | hfbits(wr[2 * kp]);
    }

    const int cA = c0 + 2 * tq;
    const int bA = mt * 16 + l4;
    float bh[3][2];
#pragma unroll
    for (int gte = 0; gte < 3; gte++) {
        bh[gte][0] = bhh[gte * HID + cA];
        bh[gte][1] = bhh[gte * HID + cA + 1];
    }

    float hp[4] = {0.f, 0.f, 0.f, 0.f};   // fp32 recurrence state, in register

    uint32_t* WST = (uint32_t*)(smraw + SM_ST_OFF) + warp * NSTG * STG_U32;
    const uint32_t s_wst = (uint32_t)__cvta_generic_to_shared(WST);

    __syncthreads();

    for (int t = 0; t < SEQ; t++) {
        float xv[3][4];
        if (wgk == 0) {
            const size_t rA = ((size_t)bA * SEQ + t) * G3;
            const size_t rB = ((size_t)(bA + 8) * SEQ + t) * G3;
#pragma unroll
            for (int gte = 0; gte < 3; gte++) {
                xv[gte][0] = __ldcg(&g_xg[rA + gte * HID + cA]);
                xv[gte][1] = __ldcg(&g_xg[rA + gte * HID + cA + 1]);
                xv[gte][2] = __ldcg(&g_xg[rB + gte * HID + cA]);
                xv[gte][3] = __ldcg(&g_xg[rB + gte * HID + cA + 1]);
            }
        }

        float acc[3][4];
#pragma unroll
        for (int nt = 0; nt < 3; nt++)
#pragma unroll
            for (int r = 0; r < 4; r++) acc[nt][r] = 0.f;

        if (t > 0) {
            bar_wait_all(base + (unsigned long long)t);

            const uint32_t* hsrc = g_hf16[t & 1];

            // per-warp stage: 16 batches x 16 u32 fp16-pairs = 64 segs, 2/lane
            auto stage = [&](int ch) {
                uint32_t dst = s_wst + (uint32_t)(ch % NSTG) * (STG_U32 * 4);
#pragma unroll
                for (int j = 0; j < 2; j++) {
                    int e = lane + 32 * j;          // 0..63
                    int b = e >> 2, s = e & 3;
                    const uint32_t* src = hsrc +
                        (size_t)(mt * 16 + b) * NKP + ch * 32 + wgk * 16 + s * 4;
                    cp_async16(dst + (uint32_t)(b * SROW + s * 4) * 4, src);
                }
                cp_commit();
            };

#pragma unroll
            for (int ch = 0; ch < NSTG - 1; ch++) stage(ch);

#pragma unroll 1
            for (int ch = 0; ch < NCH; ch++) {
                cp_wait<NSTG - 2>();
                __syncwarp();

                if (ch + NSTG - 1 < NCH) stage(ch + NSTG - 1);
                else cp_commit();

                const uint32_t* HA = WST + (ch % NSTG) * STG_U32;
#pragma unroll
                for (int ks = 0; ks < 2; ks++) {
                    const int ko = ks * 8;
                    uint32_t ah0 = HA[l4 * SROW + ko + tq];
                    uint32_t ah1 = HA[(l4 + 8) * SROW + ko + tq];
                    uint32_t ah2 = HA[l4 * SROW + ko + tq + 4];
                    uint32_t ah3 = HA[(l4 + 8) * SROW + ko + tq + 4];
                    const int kb = ch * 32 + wgk * 16 + ks * 8 + tq;
#pragma unroll
                    for (int nt = 0; nt < 3; nt++) {
                        int j = nt * 8 + l4;
                        uint32_t bh0 = WBh[j * WROW + kb];
                        uint32_t bh1 = WBh[j * WROW + kb + 4];
                        float* c = acc[nt];
                        mma_f16(c[0], c[1], c[2], c[3], ah0, ah1, ah2, ah3, bh0, bh1);
                    }
                }
            }

            cp_wait<0>();
            __syncthreads();
            float* red = (float*)(smraw + SM_ST_OFF);
            if (wgk == 1) {
                int o = (mt * 32 + lane) * 12;
#pragma unroll
                for (int nt = 0; nt < 3; nt++)
#pragma unroll
                    for (int r = 0; r < 4; r++)
                        red[o + nt * 4 + r] = acc[nt][r];
            }
            __syncthreads();
            if (wgk == 0) {
                int o = (mt * 32 + lane) * 12;
#pragma unroll
                for (int nt = 0; nt < 3; nt++)
#pragma unroll
                    for (int r = 0; r < 4; r++)
                        acc[nt][r] += red[o + nt * 4 + r];
            }
        }

        // ---- gates, fp32 in register (wg0 only) ----
        if (wgk == 0) {
            const int slot = (t + 1) & 1;
            const int kp   = 4 * bid + tq;
            float hcell[2][2];
#pragma unroll
            for (int r = 0; r < 4; r++) {
                int i  = r >> 1, jj = r & 1;
                int ar = 2 * i + jj;
                float rg = fsigmoid(xv[0][ar] + acc[0][ar] + bh[0][jj]);
                float zg = fsigmoid(xv[1][ar] + acc[1][ar] + bh[1][jj]);
                float ng = ftanh(xv[2][ar] + rg * (acc[2][ar] + bh[2][jj]));
                float h  = (1.f - zg) * ng + zg * hp[r];
                hp[r] = h;
                hcell[i][jj] = h;
            }
#pragma unroll
            for (int i = 0; i < 2; i++) {
                int b = bA + 8 * i;
                float h0 = hcell[i][0], h1 = hcell[i][1];
                g_hf16[slot][(size_t)b * NKP + kp] =
                    ((uint32_t)hfbits(h1) << 16) | hfbits(h0);

                if (ysel) {
                    uint16_t u0 = bfbits(h0), u1 = bfbits(h1);
                    uint16_t v0 = bfbits(h0 - bf2f(u0)), v1 = bfbits(h1 - bf2f(u1));
                    size_t yo = ((size_t)b * SEQ + t) * NKP + kp;
                    g_y2hi[ysel - 1][yo] = ((uint32_t)u1 << 16) | u0;
                    g_y2lo[ysel - 1][yo] = ((uint32_t)v1 << 16) | v0;
                }
                if (t == SEQ - 1) {
                    g_hb[(size_t)b * HID + cA]     = h0;
                    g_hb[(size_t)b * HID + cA + 1] = h1;
                }
            }
        }

        bar_publish(bid, base + (unsigned long long)(t + 1));
    }
}

// ---------------------------------------------------------------------------
// One-time prep: split W_ih12 into packed bf16 hi/lo pair arrays.
// ---------------------------------------------------------------------------
__global__ __launch_bounds__(256) void split_wih_kernel(
    const float* __restrict__ W12)
{
    size_t i = (size_t)blockIdx.x * 256 + threadIdx.x;
    if (i >= (size_t)2 * G3 * NKP) return;
    int    l = (int)(i / ((size_t)G3 * NKP));
    size_t r = i % ((size_t)G3 * NKP);
    size_t n = r >> 9;
    int    kp = (int)(r & (NKP - 1));
    const float* src = W12 + (size_t)l * G3 * HID + n * HID + 2 * kp;
    float w0 = src[0], w1 = src[1];
    uint16_t h0 = bfbits(w0), h1 = bfbits(w1);
    uint16_t l0 = bfbits(w0 - bf2f(h0)), l1 = bfbits(w1 - bf2f(h1));
    g_wih2hi[l][r] = ((uint32_t)h1 << 16) | h0;
    g_wih2lo[l][r] = ((uint32_t)l1 << 16) | l0;
}

// ---------------------------------------------------------------------------
// bf16 3-split MMA GEMM for xg of layers 1,2. (unchanged, passing)
// ---------------------------------------------------------------------------
#define YROW   20
#define XA_U   (128 * YROW)
#define XB_U   (64 * YROW)
#define XSTG_U (2 * XA_U + 2 * XB_U)
#define XNC    (NKP / 16)

__global__ __launch_bounds__(128, 2) void gemm_xg_bf16_kernel(
    int slot, int wsel, const float* __restrict__ bias)
{
    const uint32_t* Ahi_g = g_y2hi[slot];
    const uint32_t* Alo_g = g_y2lo[slot];
    const uint32_t* Whi_g = g_wih2hi[wsel];
    const uint32_t* Wlo_g = g_wih2lo[wsel];

    extern __shared__ uint32_t xs[];
    const int tid  = threadIdx.x;
    const int warp = tid >> 5;
    const int lane = tid & 31;
    const int g    = lane >> 2;
    const int tq   = lane & 3;

    const int n0 = blockIdx.x * 64;
    const int m0 = blockIdx.y * 128;
    const int wm = (warp & 1) * 64;
    const int wn = (warp >> 1) * 32;

    const uint32_t s_base = (uint32_t)__cvta_generic_to_shared(xs);

    float acc[4][4][4];
#pragma unroll
    for (int mi = 0; mi < 4; mi++)
#pragma unroll
        for (int ni = 0; ni < 4; ni++)
#pragma unroll
            for (int r = 0; r < 4; r++) acc[mi][ni][r] = 0.f;

    auto load_stage = [&](int ch, int buf) {
        const int kp0 = ch * 16;
        uint32_t dst = s_base + (uint32_t)buf * XSTG_U * 4;
#pragma unroll
        for (int j = 0; j < 8; j++) {
            int o = tid + j * 128;
            int arr = o >> 9, oo = o & 511;
            int row = oo >> 2, s = oo & 3;
            const uint32_t* src = (arr ? Alo_g : Ahi_g) +
                                  (size_t)(m0 + row) * NKP + kp0 + s * 4;
            cp_async16(dst + (uint32_t)(arr * XA_U + row * YROW + s * 4) * 4, src);
        }
#pragma unroll
        for (int j = 0; j < 4; j++) {
            int o = tid + j * 128;
            int arr = o >> 8, oo = o & 255;
            int row = oo >> 2, s = oo & 3;
            const uint32_t* src = (arr ? Wlo_g : Whi_g) +
                                  (size_t)(n0 + row) * NKP + kp0 + s * 4;
            cp_async16(dst + (uint32_t)(2 * XA_U + arr * XB_U + row * YROW + s * 4) * 4,
                       src);
        }
        cp_commit();
    };

    load_stage(0, 0);
    load_stage(1, 1);

    for (int ch = 0; ch < XNC; ch++) {
        cp_wait<1>();
        __syncthreads();
        const uint32_t* Ah = xs + (ch & 1) * XSTG_U;
        const uint32_t* Al = Ah + XA_U;
        const uint32_t* Bh = Ah + 2 * XA_U;
        const uint32_t* Bl = Bh + XB_U;

#pragma unroll
        for (int ks = 0; ks < 2; ks++) {
            const int ko = ks * 8;
            uint32_t ahi[4][4], alo[4][4];
#pragma unroll
            for (int mi = 0; mi < 4; mi++) {
                int rb = wm + mi * 16 + g;
                ahi[mi][0] = Ah[rb * YROW + ko + tq];
                ahi[mi][1] = Ah[(rb + 8) * YROW + ko + tq];
                ahi[mi][2] = Ah[rb * YROW + ko + tq + 4];
                ahi[mi][3] = Ah[(rb + 8) * YROW + ko + tq + 4];
                alo[mi][0] = Al[rb * YROW + ko + tq];
                alo[mi][1] = Al[(rb + 8) * YROW + ko + tq];
                alo[mi][2] = Al[rb * YROW + ko + tq + 4];
                alo[mi][3] = Al[(rb + 8) * YROW + ko + tq + 4];
            }
            uint32_t bhi[4][2], blo[4][2];
#pragma unroll
            for (int ni = 0; ni < 4; ni++) {
                int nb = wn + ni * 8 + g;
                bhi[ni][0] = Bh[nb * YROW + ko + tq];
                bhi[ni][1] = Bh[nb * YROW + ko + tq + 4];
                blo[ni][0] = Bl[nb * YROW + ko + tq];
                blo[ni][1] = Bl[nb * YROW + ko + tq + 4];
            }
#pragma unroll
            for (int mi = 0; mi < 4; mi++)
#pragma unroll
                for (int ni = 0; ni < 4; ni++) {
                    float* c = acc[mi][ni];
                    mma_bf16(c[0], c[1], c[2], c[3],
                             ahi[mi][0], ahi[mi][1], ahi[mi][2], ahi[mi][3],
                             bhi[ni][0], bhi[ni][1]);
                    mma_bf16(c[0], c[1], c[2], c[3],
                             ahi[mi][0], ahi[mi][1], ahi[mi][2], ahi[mi][3],
                             blo[ni][0], blo[ni][1]);
                    mma_bf16(c[0], c[1], c[2], c[3],
                             alo[mi][0], alo[mi][1], alo[mi][2], alo[mi][3],
                             bhi[ni][0], bhi[ni][1]);
                }
        }

        __syncthreads();
        if (ch + 2 < XNC) load_stage(ch + 2, ch & 1);
        cp_commit();
    }

#pragma unroll
    for (int mi = 0; mi < 4; mi++) {
        int r0 = m0 + wm + mi * 16 + g;
#pragma unroll
        for (int ni = 0; ni < 4; ni++) {
            int cb = n0 + wn + ni * 8 + 2 * tq;
            float2 bia = *(const float2*)&bias[cb];
            float* c = acc[mi][ni];
            *(float2*)&g_xg[(size_t)r0 * G3 + cb] =
                make_float2(c[0] + bia.x, c[1] + bia.y);
            *(float2*)&g_xg[(size_t)(r0 + 8) * G3 + cb] =
                make_float2(c[2] + bia.x, c[3] + bia.y);
        }
    }
}

// ---------------------------------------------------------------------------
// fp32 SGEMM for layer-0 xg (K = 118). (unchanged, passing)
// ---------------------------------------------------------------------------
__global__ __launch_bounds__(256) void gemm_xg_kernel(
    const float* __restrict__ x_in, int K,
    const float* __restrict__ W, const float* __restrict__ bias)
{
    const float* A = x_in;

    __shared__ float As[8][128];
    __shared__ float Bs[8][128];

    const int n0 = blockIdx.x * 128;
    const int m0 = blockIdx.y * 128;
    const int tid = threadIdx.x;
    const int tx = tid & 15;
    const int ty = tid >> 4;

    float acc[8][8];
#pragma unroll
    for (int i = 0; i < 8; i++)
#pragma unroll
        for (int j = 0; j < 8; j++) acc[i][j] = 0.f;

    const int nkt = (K + 7) >> 3;
    for (int kt = 0; kt < nkt; kt++) {
        const int k0 = kt << 3;
#pragma unroll
        for (int i = 0; i < 4; i++) {
            int ii = tid + i * 256;
            int m = ii >> 3, k = ii & 7;
            As[k][m] = (k0 + k < K) ? A[(size_t)(m0 + m) * K + (k0 + k)] : 0.f;
        }
#pragma unroll
        for (int i = 0; i < 4; i++) {
            int ii = tid + i * 256;
            int n = ii >> 3, k = ii & 7;
            Bs[k][n] = (k0 + k < K) ? W[(size_t)(n0 + n) * K + (k0 + k)] : 0.f;
        }
        __syncthreads();
#pragma unroll
        for (int k = 0; k < 8; k++) {
            float a[8], b[8];
#pragma unroll
            for (int i = 0; i < 8; i++) a[i] = As[k][ty * 8 + i];
#pragma unroll
            for (int j = 0; j < 8; j++) b[j] = Bs[k][tx * 8 + j];
#pragma unroll
            for (int i = 0; i < 8; i++)
#pragma unroll
                for (int j = 0; j < 8; j++)
                    acc[i][j] = fmaf(a[i], b[j], acc[i][j]);
        }
        __syncthreads();
    }

#pragma unroll
    for (int i = 0; i < 8; i++) {
        size_t row = (size_t)(m0 + ty * 8 + i) * G3;
#pragma unroll
        for (int j = 0; j < 8; j++) {
            int n = n0 + tx * 8 + j;
            g_xg[row + n] = acc[i][j] + bias[n];
        }
    }
}

// ---------------------------------------------------------------------------
// Final linear: out[b] = dot(h_last[b,:], W_lin) + b_lin
// ---------------------------------------------------------------------------
__global__ __launch_bounds__(256) void final_kernel(
    const float* __restrict__ Wlin, const float* __restrict__ blin,
    float* __restrict__ out)
{
    const int b = blockIdx.x;
    const float* h = g_hb + b * HID;
    float s = 0.f;
    for (int k = threadIdx.x; k < HID; k += 256) s += h[k] * Wlin[k];
#pragma unroll
    for (int o = 16; o > 0; o >>= 1) s += __shfl_down_sync(0xffffffffu, s, o);
    __shared__ float red[8];
    if ((threadIdx.x & 31) == 0) red[threadIdx.x >> 5] = s;
    __syncthreads();
    if (threadIdx.x < 8) {
        s = red[threadIdx.x];
#pragma unroll
        for (int o = 4; o > 0; o >>= 1) s += __shfl_down_sync(0xffu, s, o);
        if (threadIdx.x == 0) out[b] = s + blin[0];
    }
}

// ---------------------------------------------------------------------------
extern "C" void kernel_launch(void* const* d_in, const int* in_sizes, int n_in,
                              void* d_out, int out_size)
{
    const float* x      = (const float*)d_in[0];
    const float* W_ih0  = (const float*)d_in[1];
    const float* W_ih12 = (const float*)d_in[2];
    const float* W_hh   = (const float*)d_in[3];
    const float* b_ih   = (const float*)d_in[4];
    const float* b_hh   = (const float*)d_in[5];
    const float* W_lin  = (const float*)d_in[6];
    const float* b_lin  = (const float*)d_in[7];
    float* out = (float*)d_out;

    cudaFuncSetAttribute(gru_layer_kernel,
                         cudaFuncAttributeMaxDynamicSharedMemorySize, GSM_BYTES);
    const int smem_xgb = 2 * XSTG_U * 4;
    cudaFuncSetAttribute(gemm_xg_bf16_kernel,
                         cudaFuncAttributeMaxDynamicSharedMemorySize, smem_xgb);

    {
        size_t tot = (size_t)2 * G3 * NKP;
        split_wih_kernel<<<(unsigned)((tot + 255) / 256), 256>>>(W_ih12);
    }

    for (int l = 0; l < 3; l++) {
        const int    ysel  = (l == 0) ? 1 : (l == 1 ? 2 : 0);
        const float* Whh_l = W_hh + (size_t)l * G3 * HID;
        const float* bih_l = b_ih + (size_t)l * G3;
        const float* bhh_l = b_hh + (size_t)l * G3;

        if (l == 0) {
            dim3 ggrid(G3 / 128, BT / 128);
            gemm_xg_kernel<<<ggrid, 256>>>(x, DIN0, W_ih0, bih_l);
        } else {
            dim3 ggrid(G3 / 64, BT / 128);
            gemm_xg_bf16_kernel<<<ggrid, 128, smem_xgb>>>(l - 1, l - 1, bih_l);
        }

        gru_layer_kernel<<<NBLK, GNT, GSM_BYTES>>>(Whh_l, bhh_l, ysel);
    }

    final_kernel<<<BATCH, 256>>>(W_lin, b_lin, out);
}